// round 1
// baseline (speedup 1.0000x reference)
#include <cuda_runtime.h>

#define DIMC 512
#define HEADS 16
#define HD 32
#define SW 49
#define NWIN 64
#define BWIN 2048
#define TOKENS (BWIN * SW)   // 100352

// Scratch (static device globals; no runtime allocation)
__device__ float g_qkv[(size_t)TOKENS * 3 * DIMC];   // [tokens, 1536]
__device__ float g_att[(size_t)TOKENS * DIMC];       // [tokens, 512]

// ---------------------------------------------------------------------------
// C[M,N] = A[M,K] @ W[K,N] + bias[N]
// 64x64 block tile, K-tile 16, 256 threads, 4x4 per-thread register tile.
// Assumes M%64==0, N%64==0, K%16==0 (true for all shapes here).
// ---------------------------------------------------------------------------
__global__ void gemm_bias_kernel(const float* __restrict__ A,
                                 const float* __restrict__ W,
                                 const float* __restrict__ bias,
                                 float* __restrict__ C,
                                 int M, int N, int K) {
    __shared__ float As[16][64];   // [k][m]
    __shared__ float Ws[16][64];   // [k][n]

    const int tid = threadIdx.x;          // 0..255
    const int tx = tid & 15;              // 0..15
    const int ty = tid >> 4;              // 0..15
    const int m0 = blockIdx.y * 64;
    const int n0 = blockIdx.x * 64;

    // A tile load mapping: 64 rows x 16 cols, one float4 per thread
    const int ar = tid >> 2;              // 0..63
    const int ac = (tid & 3) * 4;         // 0,4,8,12
    // W tile load mapping: 16 rows x 64 cols, one float4 per thread
    const int wr = tid >> 4;              // 0..15
    const int wc = (tid & 15) * 4;        // 0..60

    float acc[4][4];
#pragma unroll
    for (int i = 0; i < 4; i++)
#pragma unroll
        for (int j = 0; j < 4; j++) acc[i][j] = 0.f;

    for (int k0 = 0; k0 < K; k0 += 16) {
        float4 av = *(const float4*)&A[(size_t)(m0 + ar) * K + k0 + ac];
        As[ac + 0][ar] = av.x;
        As[ac + 1][ar] = av.y;
        As[ac + 2][ar] = av.z;
        As[ac + 3][ar] = av.w;
        *(float4*)&Ws[wr][wc] =
            *(const float4*)&W[(size_t)(k0 + wr) * N + n0 + wc];
        __syncthreads();

#pragma unroll
        for (int k = 0; k < 16; k++) {
            float4 a = *(const float4*)&As[k][ty * 4];
            float4 b = *(const float4*)&Ws[k][tx * 4];
            float aa[4] = {a.x, a.y, a.z, a.w};
            float bb[4] = {b.x, b.y, b.z, b.w};
#pragma unroll
            for (int i = 0; i < 4; i++)
#pragma unroll
                for (int j = 0; j < 4; j++) acc[i][j] += aa[i] * bb[j];
        }
        __syncthreads();
    }

#pragma unroll
    for (int i = 0; i < 4; i++) {
        const int row = m0 + ty * 4 + i;
#pragma unroll
        for (int j = 0; j < 4; j++) {
            const int col = n0 + tx * 4 + j;
            C[(size_t)row * N + col] = acc[i][j] + bias[col];
        }
    }
}

// ---------------------------------------------------------------------------
// One block per (window b, head h). 128 threads.
// scores = scale*q@k^T + bias[rel_idx] + mask[b%NWIN]; softmax; out = p@v
// Reads g_qkv, writes g_att in [token, h*HD+d] layout (ready for proj GEMM).
// ---------------------------------------------------------------------------
__global__ void attn_kernel(const float* __restrict__ mask,
                            const float* __restrict__ bias_table,
                            const int* __restrict__ rel_idx) {
    __shared__ float qs[SW][HD + 1];
    __shared__ float ks[SW][HD + 1];
    __shared__ float vs[SW][HD + 1];
    __shared__ float at[SW][SW];

    const int bh = blockIdx.x;
    const int b = bh / HEADS;
    const int h = bh % HEADS;
    const int tid = threadIdx.x;          // 0..127
    const float scale = 0.17677669529663689f;   // 32^-0.5

    const float* qkv = g_qkv + (size_t)b * SW * (3 * DIMC);

    for (int e = tid; e < SW * HD; e += 128) {
        const int s = e / HD, d = e % HD;
        const size_t base = (size_t)s * (3 * DIMC) + h * HD + d;
        qs[s][d] = qkv[base] * scale;
        ks[s][d] = qkv[base + DIMC];
        vs[s][d] = qkv[base + 2 * DIMC];
    }
    __syncthreads();

    const float* mrow = mask + (size_t)(b % NWIN) * SW * SW;
    for (int e = tid; e < SW * SW; e += 128) {
        const int i = e / SW, j = e % SW;
        float acc = 0.f;
#pragma unroll
        for (int d = 0; d < HD; d++) acc += qs[i][d] * ks[j][d];
        at[i][j] = acc + bias_table[rel_idx[e] * HEADS + h] + mrow[e];
    }
    __syncthreads();

    if (tid < SW) {
        float m = -1e30f;
#pragma unroll
        for (int j = 0; j < SW; j++) m = fmaxf(m, at[tid][j]);
        float sum = 0.f;
#pragma unroll
        for (int j = 0; j < SW; j++) {
            float e2 = __expf(at[tid][j] - m);
            at[tid][j] = e2;
            sum += e2;
        }
        const float inv = 1.f / sum;
#pragma unroll
        for (int j = 0; j < SW; j++) at[tid][j] *= inv;
    }
    __syncthreads();

    float* out = g_att + (size_t)b * SW * DIMC;
    for (int e = tid; e < SW * HD; e += 128) {
        const int i = e / HD, d = e % HD;
        float acc = 0.f;
#pragma unroll
        for (int j = 0; j < SW; j++) acc += at[i][j] * vs[j][d];
        out[(size_t)i * DIMC + h * HD + d] = acc;
    }
}

// ---------------------------------------------------------------------------
extern "C" void kernel_launch(void* const* d_in, const int* in_sizes, int n_in,
                              void* d_out, int out_size) {
    const float* x          = (const float*)d_in[0];
    const float* mask       = (const float*)d_in[1];
    const float* qkv_w      = (const float*)d_in[2];
    const float* qkv_b      = (const float*)d_in[3];
    const float* proj_w     = (const float*)d_in[4];
    const float* proj_b     = (const float*)d_in[5];
    const float* bias_table = (const float*)d_in[6];
    const int*   rel_idx    = (const int*)d_in[7];

    static float* qkv_ptr = nullptr;
    static float* att_ptr = nullptr;
    if (!qkv_ptr) {
        cudaGetSymbolAddress((void**)&qkv_ptr, g_qkv);
        cudaGetSymbolAddress((void**)&att_ptr, g_att);
    }

    // 1) QKV projection: [100352,512] x [512,1536] + b
    gemm_bias_kernel<<<dim3(3 * DIMC / 64, TOKENS / 64), 256>>>(
        x, qkv_w, qkv_b, qkv_ptr, TOKENS, 3 * DIMC, DIMC);

    // 2) Windowed attention per (window, head)
    attn_kernel<<<BWIN * HEADS, 128>>>(mask, bias_table, rel_idx);

    // 3) Output projection: [100352,512] x [512,512] + b -> d_out
    gemm_bias_kernel<<<dim3(DIMC / 64, TOKENS / 64), 256>>>(
        att_ptr, proj_w, proj_b, (float*)d_out, TOKENS, DIMC, DIMC);
}

// round 2
// speedup vs baseline: 2.5267x; 2.5267x over previous
#include <cuda_runtime.h>

#define DIMC 512
#define HEADS 16
#define HD 32
#define SW 49
#define NWIN 64
#define BWIN 2048
#define TOKENS (BWIN * SW)   // 100352

// Scratch (static device globals; no runtime allocation)
__device__ float g_qkv[(size_t)TOKENS * 3 * DIMC];   // [tokens, 1536]
__device__ float g_att[(size_t)TOKENS * DIMC];       // [tokens, 512]

__device__ __forceinline__ unsigned f2tf32(float f) {
    unsigned u;
    asm("cvt.rna.tf32.f32 %0, %1;" : "=r"(u) : "f"(f));
    return u;
}

__device__ __forceinline__ void mma_tf32(float* d, const unsigned* a, const unsigned* b) {
    asm volatile(
        "mma.sync.aligned.m16n8k8.row.col.f32.tf32.tf32.f32 "
        "{%0,%1,%2,%3}, {%4,%5,%6,%7}, {%8,%9}, {%0,%1,%2,%3};"
        : "+f"(d[0]), "+f"(d[1]), "+f"(d[2]), "+f"(d[3])
        : "r"(a[0]), "r"(a[1]), "r"(a[2]), "r"(a[3]), "r"(b[0]), "r"(b[1]));
}

// ---------------------------------------------------------------------------
// C[M,N] = A[M,K] @ W[K,N] + bias[N]  (tf32 tensor-core path)
// Block tile 128x128x16, 256 threads, 8 warps (2m x 4n), warp tile 64x32.
// Requires M%128==0, N%128==0, K%16==0.
// ---------------------------------------------------------------------------
__global__ __launch_bounds__(256) void gemm_tf32_kernel(
        const float* __restrict__ A, const float* __restrict__ W,
        const float* __restrict__ bias, float* __restrict__ C,
        int M, int N, int K) {
    // Padded, conflict-free layouts (see analysis): A [m][k] stride 20, B [k][n] stride 136
    __shared__ unsigned As[2][128][20];
    __shared__ unsigned Bs[2][16][136];

    const int tid = threadIdx.x;
    const int lane = tid & 31;
    const int wid = tid >> 5;
    const int wm = (wid >> 2) * 64;     // warp m offset within block
    const int wn = (wid & 3) * 32;      // warp n offset within block
    const int m0 = blockIdx.y * 128;
    const int n0 = blockIdx.x * 128;

    // Global-load mapping (2 float4 per thread for each of A and B tiles)
    // A tile: 128 rows x 16 cols;  B tile: 16 rows x 128 cols
    const int a_r[2] = { tid >> 2, (tid + 256) >> 2 };
    const int a_c = (tid & 3) << 2;
    const int b_r[2] = { tid >> 5, (tid + 256) >> 5 };
    const int b_c = (tid & 31) << 2;

    float4 aReg[2], bReg[2];
    float acc[4][4][4];
#pragma unroll
    for (int mt = 0; mt < 4; mt++)
#pragma unroll
        for (int nt = 0; nt < 4; nt++)
#pragma unroll
            for (int r = 0; r < 4; r++) acc[mt][nt][r] = 0.f;

    const int nIter = K >> 4;

    // prologue: load tile 0
#pragma unroll
    for (int i = 0; i < 2; i++) {
        aReg[i] = *(const float4*)&A[(size_t)(m0 + a_r[i]) * K + a_c];
        bReg[i] = *(const float4*)&W[(size_t)(b_r[i]) * N + n0 + b_c];
    }
#pragma unroll
    for (int i = 0; i < 2; i++) {
        unsigned* pa = &As[0][a_r[i]][a_c];
        pa[0] = f2tf32(aReg[i].x); pa[1] = f2tf32(aReg[i].y);
        pa[2] = f2tf32(aReg[i].z); pa[3] = f2tf32(aReg[i].w);
        unsigned* pb = &Bs[0][b_r[i]][b_c];
        pb[0] = f2tf32(bReg[i].x); pb[1] = f2tf32(bReg[i].y);
        pb[2] = f2tf32(bReg[i].z); pb[3] = f2tf32(bReg[i].w);
    }
    __syncthreads();

    for (int it = 0; it < nIter; it++) {
        const int buf = it & 1;
        // prefetch next tile into registers
        if (it + 1 < nIter) {
            const int k0 = (it + 1) << 4;
#pragma unroll
            for (int i = 0; i < 2; i++) {
                aReg[i] = *(const float4*)&A[(size_t)(m0 + a_r[i]) * K + k0 + a_c];
                bReg[i] = *(const float4*)&W[(size_t)(k0 + b_r[i]) * N + n0 + b_c];
            }
        }

        // compute on current buffer: 2 k-steps of 8
#pragma unroll
        for (int ks = 0; ks < 2; ks++) {
            unsigned afr[4][4], bfr[4][2];
            const int ac2 = ks * 8 + (lane & 3);
            const int arr = wm + (lane >> 2);
#pragma unroll
            for (int mt = 0; mt < 4; mt++) {
                const int r = arr + mt * 16;
                afr[mt][0] = As[buf][r][ac2];
                afr[mt][1] = As[buf][r + 8][ac2];
                afr[mt][2] = As[buf][r][ac2 + 4];
                afr[mt][3] = As[buf][r + 8][ac2 + 4];
            }
            const int brr = ks * 8 + (lane & 3);
            const int bcc = wn + (lane >> 2);
#pragma unroll
            for (int nt = 0; nt < 4; nt++) {
                bfr[nt][0] = Bs[buf][brr][bcc + nt * 8];
                bfr[nt][1] = Bs[buf][brr + 4][bcc + nt * 8];
            }
#pragma unroll
            for (int mt = 0; mt < 4; mt++)
#pragma unroll
                for (int nt = 0; nt < 4; nt++)
                    mma_tf32(acc[mt][nt], afr[mt], bfr[nt]);
        }

        // stage next tile into the other buffer
        if (it + 1 < nIter) {
            const int nb = buf ^ 1;
#pragma unroll
            for (int i = 0; i < 2; i++) {
                unsigned* pa = &As[nb][a_r[i]][a_c];
                pa[0] = f2tf32(aReg[i].x); pa[1] = f2tf32(aReg[i].y);
                pa[2] = f2tf32(aReg[i].z); pa[3] = f2tf32(aReg[i].w);
                unsigned* pb = &Bs[nb][b_r[i]][b_c];
                pb[0] = f2tf32(bReg[i].x); pb[1] = f2tf32(bReg[i].y);
                pb[2] = f2tf32(bReg[i].z); pb[3] = f2tf32(bReg[i].w);
            }
            __syncthreads();
        }
    }

    // epilogue: C = acc + bias
#pragma unroll
    for (int mt = 0; mt < 4; mt++) {
        const int r = m0 + wm + mt * 16 + (lane >> 2);
#pragma unroll
        for (int nt = 0; nt < 4; nt++) {
            const int c = n0 + wn + nt * 8 + ((lane & 3) << 1);
            float2 o0 = make_float2(acc[mt][nt][0] + bias[c],
                                    acc[mt][nt][1] + bias[c + 1]);
            float2 o1 = make_float2(acc[mt][nt][2] + bias[c],
                                    acc[mt][nt][3] + bias[c + 1]);
            *(float2*)&C[(size_t)r * N + c] = o0;
            *(float2*)&C[(size_t)(r + 8) * N + c] = o1;
        }
    }
}

// ---------------------------------------------------------------------------
// One block per (window b, head h). 128 threads.
// ---------------------------------------------------------------------------
__global__ void attn_kernel(const float* __restrict__ mask,
                            const float* __restrict__ bias_table,
                            const int* __restrict__ rel_idx) {
    __shared__ float qs[SW][HD + 1];
    __shared__ float ks[SW][HD + 1];
    __shared__ float vs[SW][HD + 1];
    __shared__ float at[SW][SW];

    const int bh = blockIdx.x;
    const int b = bh / HEADS;
    const int h = bh % HEADS;
    const int tid = threadIdx.x;
    const float scale = 0.17677669529663689f;

    const float* qkv = g_qkv + (size_t)b * SW * (3 * DIMC);

    for (int e = tid; e < SW * HD; e += 128) {
        const int s = e / HD, d = e % HD;
        const size_t base = (size_t)s * (3 * DIMC) + h * HD + d;
        qs[s][d] = qkv[base] * scale;
        ks[s][d] = qkv[base + DIMC];
        vs[s][d] = qkv[base + 2 * DIMC];
    }
    __syncthreads();

    const float* mrow = mask + (size_t)(b % NWIN) * SW * SW;
    for (int e = tid; e < SW * SW; e += 128) {
        const int i = e / SW, j = e % SW;
        float acc = 0.f;
#pragma unroll
        for (int d = 0; d < HD; d++) acc += qs[i][d] * ks[j][d];
        at[i][j] = acc + bias_table[rel_idx[e] * HEADS + h] + mrow[e];
    }
    __syncthreads();

    if (tid < SW) {
        float m = -1e30f;
#pragma unroll
        for (int j = 0; j < SW; j++) m = fmaxf(m, at[tid][j]);
        float sum = 0.f;
#pragma unroll
        for (int j = 0; j < SW; j++) {
            float e2 = __expf(at[tid][j] - m);
            at[tid][j] = e2;
            sum += e2;
        }
        const float inv = 1.f / sum;
#pragma unroll
        for (int j = 0; j < SW; j++) at[tid][j] *= inv;
    }
    __syncthreads();

    float* out = g_att + (size_t)b * SW * DIMC;
    for (int e = tid; e < SW * HD; e += 128) {
        const int i = e / HD, d = e % HD;
        float acc = 0.f;
#pragma unroll
        for (int j = 0; j < SW; j++) acc += at[i][j] * vs[j][d];
        out[(size_t)i * DIMC + h * HD + d] = acc;
    }
}

// ---------------------------------------------------------------------------
extern "C" void kernel_launch(void* const* d_in, const int* in_sizes, int n_in,
                              void* d_out, int out_size) {
    const float* x          = (const float*)d_in[0];
    const float* mask       = (const float*)d_in[1];
    const float* qkv_w      = (const float*)d_in[2];
    const float* qkv_b      = (const float*)d_in[3];
    const float* proj_w     = (const float*)d_in[4];
    const float* proj_b     = (const float*)d_in[5];
    const float* bias_table = (const float*)d_in[6];
    const int*   rel_idx    = (const int*)d_in[7];

    static float* qkv_ptr = nullptr;
    static float* att_ptr = nullptr;
    if (!qkv_ptr) {
        cudaGetSymbolAddress((void**)&qkv_ptr, g_qkv);
        cudaGetSymbolAddress((void**)&att_ptr, g_att);
    }

    // 1) QKV projection: [100352,512] x [512,1536] + b
    gemm_tf32_kernel<<<dim3(3 * DIMC / 128, TOKENS / 128), 256>>>(
        x, qkv_w, qkv_b, qkv_ptr, TOKENS, 3 * DIMC, DIMC);

    // 2) Windowed attention per (window, head)
    attn_kernel<<<BWIN * HEADS, 128>>>(mask, bias_table, rel_idx);

    // 3) Output projection: [100352,512] x [512,512] + b -> d_out
    gemm_tf32_kernel<<<dim3(DIMC / 128, TOKENS / 128), 256>>>(
        att_ptr, proj_w, proj_b, (float*)d_out, TOKENS, DIMC, DIMC);
}

// round 3
// speedup vs baseline: 2.6149x; 1.0349x over previous
#include <cuda_runtime.h>
#include <cstdint>

#define DIMC 512
#define HEADS 16
#define HD 32
#define SW 49
#define NWIN 64
#define BWIN 2048
#define TOKENS (BWIN * SW)   // 100352

#define SA 20                 // smem row stride in words (conflict-free for ldmatrix)
#define BUFW (128 * SA)       // words per tile buffer

// Scratch (static device globals; no runtime allocation)
__device__ float g_qkv[(size_t)TOKENS * 3 * DIMC];   // [tokens, 1536]
__device__ float g_att[(size_t)TOKENS * DIMC];       // [tokens, 512]

__device__ __forceinline__ unsigned f2tf32(float f) {
    unsigned u;
    asm("cvt.rna.tf32.f32 %0, %1;" : "=r"(u) : "f"(f));
    return u;
}

__device__ __forceinline__ void mma_tf32(float* d, const unsigned* a, const unsigned* b) {
    asm volatile(
        "mma.sync.aligned.m16n8k8.row.col.f32.tf32.tf32.f32 "
        "{%0,%1,%2,%3}, {%4,%5,%6,%7}, {%8,%9}, {%0,%1,%2,%3};"
        : "+f"(d[0]), "+f"(d[1]), "+f"(d[2]), "+f"(d[3])
        : "r"(a[0]), "r"(a[1]), "r"(a[2]), "r"(a[3]), "r"(b[0]), "r"(b[1]));
}

__device__ __forceinline__ void ldsm4(unsigned& r0, unsigned& r1,
                                      unsigned& r2, unsigned& r3, uint32_t addr) {
    asm volatile("ldmatrix.sync.aligned.m8n8.x4.shared.b16 {%0,%1,%2,%3}, [%4];"
                 : "=r"(r0), "=r"(r1), "=r"(r2), "=r"(r3) : "r"(addr));
}

// ---------------------------------------------------------------------------
// C[M,N] = A[M,K] @ W[K,N] + bias[N]  (tf32 mma + ldmatrix fragment loads)
// Block tile 128x128x16, 256 threads, 8 warps (2m x 4n), warp tile 64x32.
// A smem [row][k] stride 20; B smem TRANSPOSED [n][k] stride 20.
// ---------------------------------------------------------------------------
__global__ __launch_bounds__(256) void gemm_tf32_kernel(
        const float* __restrict__ A, const float* __restrict__ W,
        const float* __restrict__ bias, float* __restrict__ C,
        int M, int N, int K) {
    __shared__ unsigned As[2 * BUFW];
    __shared__ unsigned Bs[2 * BUFW];

    const int tid = threadIdx.x;
    const int lane = tid & 31;
    const int wid = tid >> 5;
    const int wm = (wid >> 2) * 64;
    const int wn = (wid & 3) * 32;
    const int m0 = blockIdx.y * 128;
    const int n0 = blockIdx.x * 128;

    // A staging: 128 rows x 16 k; thread -> rows {a_r, a_r+64}, 4 consecutive k
    const int a_r = tid >> 2;            // 0..63
    const int a_c = (tid & 3) << 2;      // 0,4,8,12
    // B staging (transposed): thread -> fixed n, 8 consecutive k
    const int b_n = tid & 127;           // 0..127
    const int b_kh = (tid >> 7) << 3;    // 0 or 8

    // ldmatrix per-lane bases
    const int lm = lane >> 3, lr = lane & 7;
    const unsigned aBaseW = (unsigned)((wm + ((lm & 1) << 3) + lr) * SA + ((lm >> 1) << 2));
    const unsigned bBaseW = (unsigned)((wn + ((lm >> 1) << 3) + lr) * SA + ((lm & 1) << 2));
    const uint32_t asA = (uint32_t)__cvta_generic_to_shared(As);
    const uint32_t asB = (uint32_t)__cvta_generic_to_shared(Bs);

    float4 aReg[2];
    float bReg[8];
    float acc[4][4][4];
#pragma unroll
    for (int mt = 0; mt < 4; mt++)
#pragma unroll
        for (int nt = 0; nt < 4; nt++)
#pragma unroll
            for (int r = 0; r < 4; r++) acc[mt][nt][r] = 0.f;

    const int nIter = K >> 4;

    // ---- prologue: tile 0 ----
    aReg[0] = *(const float4*)&A[(size_t)(m0 + a_r) * K + a_c];
    aReg[1] = *(const float4*)&A[(size_t)(m0 + a_r + 64) * K + a_c];
#pragma unroll
    for (int i = 0; i < 8; i++)
        bReg[i] = W[(size_t)(b_kh + i) * N + n0 + b_n];
    {
        uint4 pa0 = make_uint4(f2tf32(aReg[0].x), f2tf32(aReg[0].y),
                               f2tf32(aReg[0].z), f2tf32(aReg[0].w));
        uint4 pa1 = make_uint4(f2tf32(aReg[1].x), f2tf32(aReg[1].y),
                               f2tf32(aReg[1].z), f2tf32(aReg[1].w));
        *(uint4*)&As[a_r * SA + a_c] = pa0;
        *(uint4*)&As[(a_r + 64) * SA + a_c] = pa1;
        uint4 pb0 = make_uint4(f2tf32(bReg[0]), f2tf32(bReg[1]),
                               f2tf32(bReg[2]), f2tf32(bReg[3]));
        uint4 pb1 = make_uint4(f2tf32(bReg[4]), f2tf32(bReg[5]),
                               f2tf32(bReg[6]), f2tf32(bReg[7]));
        *(uint4*)&Bs[b_n * SA + b_kh] = pb0;
        *(uint4*)&Bs[b_n * SA + b_kh + 4] = pb1;
    }
    __syncthreads();

    for (int it = 0; it < nIter; it++) {
        const int buf = it & 1;

        // prefetch next tile into registers
        if (it + 1 < nIter) {
            const int k0 = (it + 1) << 4;
            aReg[0] = *(const float4*)&A[(size_t)(m0 + a_r) * K + k0 + a_c];
            aReg[1] = *(const float4*)&A[(size_t)(m0 + a_r + 64) * K + k0 + a_c];
#pragma unroll
            for (int i = 0; i < 8; i++)
                bReg[i] = W[(size_t)(k0 + b_kh + i) * N + n0 + b_n];
        }

        // compute on current buffer: 2 k-steps of 8
#pragma unroll
        for (int ks = 0; ks < 2; ks++) {
            unsigned afr[4][4];
#pragma unroll
            for (int mt = 0; mt < 4; mt++) {
                uint32_t addr = asA +
                    ((unsigned)(buf * BUFW + mt * 16 * SA + ks * 8) + aBaseW) * 4u;
                ldsm4(afr[mt][0], afr[mt][1], afr[mt][2], afr[mt][3], addr);
            }
            unsigned bfr[4][2];
#pragma unroll
            for (int p = 0; p < 2; p++) {
                uint32_t addr = asB +
                    ((unsigned)(buf * BUFW + p * 16 * SA + ks * 8) + bBaseW) * 4u;
                unsigned r0, r1, r2, r3;
                ldsm4(r0, r1, r2, r3, addr);
                bfr[2 * p][0] = r0;     bfr[2 * p][1] = r1;
                bfr[2 * p + 1][0] = r2; bfr[2 * p + 1][1] = r3;
            }
#pragma unroll
            for (int mt = 0; mt < 4; mt++)
#pragma unroll
                for (int nt = 0; nt < 4; nt++)
                    mma_tf32(acc[mt][nt], afr[mt], bfr[nt]);
        }

        // stage next tile into the other buffer
        if (it + 1 < nIter) {
            const int nb = buf ^ 1;
            uint4 pa0 = make_uint4(f2tf32(aReg[0].x), f2tf32(aReg[0].y),
                                   f2tf32(aReg[0].z), f2tf32(aReg[0].w));
            uint4 pa1 = make_uint4(f2tf32(aReg[1].x), f2tf32(aReg[1].y),
                                   f2tf32(aReg[1].z), f2tf32(aReg[1].w));
            *(uint4*)&As[nb * BUFW + a_r * SA + a_c] = pa0;
            *(uint4*)&As[nb * BUFW + (a_r + 64) * SA + a_c] = pa1;
            uint4 pb0 = make_uint4(f2tf32(bReg[0]), f2tf32(bReg[1]),
                                   f2tf32(bReg[2]), f2tf32(bReg[3]));
            uint4 pb1 = make_uint4(f2tf32(bReg[4]), f2tf32(bReg[5]),
                                   f2tf32(bReg[6]), f2tf32(bReg[7]));
            *(uint4*)&Bs[nb * BUFW + b_n * SA + b_kh] = pb0;
            *(uint4*)&Bs[nb * BUFW + b_n * SA + b_kh + 4] = pb1;
            __syncthreads();
        }
    }

    // epilogue: C = acc + bias
#pragma unroll
    for (int mt = 0; mt < 4; mt++) {
        const int r = m0 + wm + mt * 16 + (lane >> 2);
#pragma unroll
        for (int nt = 0; nt < 4; nt++) {
            const int c = n0 + wn + nt * 8 + ((lane & 3) << 1);
            float2 o0 = make_float2(acc[mt][nt][0] + bias[c],
                                    acc[mt][nt][1] + bias[c + 1]);
            float2 o1 = make_float2(acc[mt][nt][2] + bias[c],
                                    acc[mt][nt][3] + bias[c + 1]);
            *(float2*)&C[(size_t)r * N + c] = o0;
            *(float2*)&C[(size_t)(r + 8) * N + c] = o1;
        }
    }
}

// ---------------------------------------------------------------------------
// One block per (window b, head h). 128 threads.
// ---------------------------------------------------------------------------
__global__ void attn_kernel(const float* __restrict__ mask,
                            const float* __restrict__ bias_table,
                            const int* __restrict__ rel_idx) {
    __shared__ float qs[SW][HD + 1];
    __shared__ float ks[SW][HD + 1];
    __shared__ float vs[SW][HD + 1];
    __shared__ float at[SW][SW];

    const int bh = blockIdx.x;
    const int b = bh / HEADS;
    const int h = bh % HEADS;
    const int tid = threadIdx.x;
    const float scale = 0.17677669529663689f;

    const float* qkv = g_qkv + (size_t)b * SW * (3 * DIMC);

    for (int e = tid; e < SW * HD; e += 128) {
        const int s = e / HD, d = e % HD;
        const size_t base = (size_t)s * (3 * DIMC) + h * HD + d;
        qs[s][d] = qkv[base] * scale;
        ks[s][d] = qkv[base + DIMC];
        vs[s][d] = qkv[base + 2 * DIMC];
    }
    __syncthreads();

    const float* mrow = mask + (size_t)(b % NWIN) * SW * SW;
    for (int e = tid; e < SW * SW; e += 128) {
        const int i = e / SW, j = e % SW;
        float acc = 0.f;
#pragma unroll
        for (int d = 0; d < HD; d++) acc += qs[i][d] * ks[j][d];
        at[i][j] = acc + bias_table[rel_idx[e] * HEADS + h] + mrow[e];
    }
    __syncthreads();

    if (tid < SW) {
        float m = -1e30f;
#pragma unroll
        for (int j = 0; j < SW; j++) m = fmaxf(m, at[tid][j]);
        float sum = 0.f;
#pragma unroll
        for (int j = 0; j < SW; j++) {
            float e2 = __expf(at[tid][j] - m);
            at[tid][j] = e2;
            sum += e2;
        }
        const float inv = 1.f / sum;
#pragma unroll
        for (int j = 0; j < SW; j++) at[tid][j] *= inv;
    }
    __syncthreads();

    float* out = g_att + (size_t)b * SW * DIMC;
    for (int e = tid; e < SW * HD; e += 128) {
        const int i = e / HD, d = e % HD;
        float acc = 0.f;
#pragma unroll
        for (int j = 0; j < SW; j++) acc += at[i][j] * vs[j][d];
        out[(size_t)i * DIMC + h * HD + d] = acc;
    }
}

// ---------------------------------------------------------------------------
extern "C" void kernel_launch(void* const* d_in, const int* in_sizes, int n_in,
                              void* d_out, int out_size) {
    const float* x          = (const float*)d_in[0];
    const float* mask       = (const float*)d_in[1];
    const float* qkv_w      = (const float*)d_in[2];
    const float* qkv_b      = (const float*)d_in[3];
    const float* proj_w     = (const float*)d_in[4];
    const float* proj_b     = (const float*)d_in[5];
    const float* bias_table = (const float*)d_in[6];
    const int*   rel_idx    = (const int*)d_in[7];

    static float* qkv_ptr = nullptr;
    static float* att_ptr = nullptr;
    if (!qkv_ptr) {
        cudaGetSymbolAddress((void**)&qkv_ptr, g_qkv);
        cudaGetSymbolAddress((void**)&att_ptr, g_att);
    }

    // 1) QKV projection: [100352,512] x [512,1536] + b
    gemm_tf32_kernel<<<dim3(3 * DIMC / 128, TOKENS / 128), 256>>>(
        x, qkv_w, qkv_b, qkv_ptr, TOKENS, 3 * DIMC, DIMC);

    // 2) Windowed attention per (window, head)
    attn_kernel<<<BWIN * HEADS, 128>>>(mask, bias_table, rel_idx);

    // 3) Output projection: [100352,512] x [512,512] + b -> d_out
    gemm_tf32_kernel<<<dim3(DIMC / 128, TOKENS / 128), 256>>>(
        att_ptr, proj_w, proj_b, (float*)d_out, TOKENS, DIMC, DIMC);
}

// round 4
// speedup vs baseline: 2.6665x; 1.0197x over previous
#include <cuda_runtime.h>
#include <cstdint>

#define DIMC 512
#define HEADS 16
#define HD 32
#define SW 49
#define NWIN 64
#define BWIN 2048
#define TOKENS (BWIN * SW)   // 100352

#define SA 20                 // smem row stride in words (conflict-free, 16B-aligned: 80B)
#define BUFW (128 * SA)       // words per tile buffer per matrix
#define STAGES 4
#define GEMM_SMEM (2 * STAGES * BUFW * 4)   // bytes

// Scratch (static device globals; no runtime allocation)
__device__ float g_qkv[(size_t)TOKENS * 3 * DIMC];    // [tokens, 1536] fp32 (+bias)
__device__ float g_att[(size_t)TOKENS * DIMC];        // [tokens, 512] tf32-rounded
__device__ float g_convx[(size_t)TOKENS * DIMC];      // x, tf32-rounded
__device__ float g_wtq[(size_t)(3 * DIMC) * DIMC];    // qkv_w^T [n][k] tf32-rounded
__device__ float g_wtp[(size_t)DIMC * DIMC];          // proj_w^T [n][k] tf32-rounded

__device__ __forceinline__ unsigned f2tf32(float f) {
    unsigned u;
    asm("cvt.rna.tf32.f32 %0, %1;" : "=r"(u) : "f"(f));
    return u;
}
__device__ __forceinline__ float f2tf32f(float f) { return __uint_as_float(f2tf32(f)); }

__device__ __forceinline__ void mma_tf32(float* d, const unsigned* a, const unsigned* b) {
    asm volatile(
        "mma.sync.aligned.m16n8k8.row.col.f32.tf32.tf32.f32 "
        "{%0,%1,%2,%3}, {%4,%5,%6,%7}, {%8,%9}, {%0,%1,%2,%3};"
        : "+f"(d[0]), "+f"(d[1]), "+f"(d[2]), "+f"(d[3])
        : "r"(a[0]), "r"(a[1]), "r"(a[2]), "r"(a[3]), "r"(b[0]), "r"(b[1]));
}

__device__ __forceinline__ void ldsm4(unsigned& r0, unsigned& r1,
                                      unsigned& r2, unsigned& r3, uint32_t addr) {
    asm volatile("ldmatrix.sync.aligned.m8n8.x4.shared.b16 {%0,%1,%2,%3}, [%4];"
                 : "=r"(r0), "=r"(r1), "=r"(r2), "=r"(r3) : "r"(addr));
}

__device__ __forceinline__ void cpasync16(uint32_t dst, const void* src) {
    asm volatile("cp.async.cg.shared.global [%0], [%1], 16;" :: "r"(dst), "l"(src));
}

// ---------------------------------------------------------------------------
// Pre-pass: tf32-round a contiguous fp32 array (float4 granularity)
// ---------------------------------------------------------------------------
__global__ void cvt_kernel(const float4* __restrict__ src, float4* __restrict__ dst, int n4) {
    int i = blockIdx.x * blockDim.x + threadIdx.x;
    if (i < n4) {
        float4 v = src[i];
        dst[i] = make_float4(f2tf32f(v.x), f2tf32f(v.y), f2tf32f(v.z), f2tf32f(v.w));
    }
}

// Pre-pass: Wt[n*K + k] = tf32(W[k*N + n]);  32x32 tiles, 32x8 threads
__global__ void tconv_kernel(const float* __restrict__ W, float* __restrict__ Wt,
                             int K, int N) {
    __shared__ float t[32][33];
    const int n0 = blockIdx.x * 32, k0 = blockIdx.y * 32;
    const int tx = threadIdx.x, ty = threadIdx.y;
#pragma unroll
    for (int r = 0; r < 32; r += 8)
        t[ty + r][tx] = W[(size_t)(k0 + ty + r) * N + n0 + tx];
    __syncthreads();
#pragma unroll
    for (int r = 0; r < 32; r += 8)
        Wt[(size_t)(n0 + ty + r) * K + k0 + tx] = f2tf32f(t[tx][ty + r]);
}

// ---------------------------------------------------------------------------
// C[M,N] = A[M,K] @ Wt[N,K]^T + bias[N]   (A, Wt pre-rounded to tf32)
// Block tile 128x128x16, 256 threads, 8 warps (2m x 4n), warp tile 64x32.
// 4-stage cp.async pipeline; both smem tiles [row][k] stride SA.
// ---------------------------------------------------------------------------
__global__ __launch_bounds__(256) void gemm_tf32_kernel(
        const float* __restrict__ A, const float* __restrict__ Wt,
        const float* __restrict__ bias, float* __restrict__ C,
        int M, int N, int K) {
    extern __shared__ unsigned sh[];
    unsigned* As = sh;                       // STAGES*BUFW
    unsigned* Bs = sh + STAGES * BUFW;

    const int tid = threadIdx.x;
    const int lane = tid & 31;
    const int wid = tid >> 5;
    const int wm = (wid >> 2) * 64;
    const int wn = (wid & 3) * 32;
    const int m0 = blockIdx.y * 128;
    const int n0 = blockIdx.x * 128;

    // tile staging: 128 rows x 16 k; 2 x 16B per thread per matrix
    const int s_r = tid >> 2;            // 0..63 (second op at +64)
    const int s_c = (tid & 3) << 2;      // 0,4,8,12

    // ldmatrix per-lane bases (validated layout from round 3)
    const int lm = lane >> 3, lr = lane & 7;
    const unsigned aBaseW = (unsigned)((wm + ((lm & 1) << 3) + lr) * SA + ((lm >> 1) << 2));
    const unsigned bBaseW = (unsigned)((wn + ((lm >> 1) << 3) + lr) * SA + ((lm & 1) << 2));
    const uint32_t asA = (uint32_t)__cvta_generic_to_shared(As);
    const uint32_t asB = (uint32_t)__cvta_generic_to_shared(Bs);

    float acc[4][4][4];
#pragma unroll
    for (int mt = 0; mt < 4; mt++)
#pragma unroll
        for (int nt = 0; nt < 4; nt++)
#pragma unroll
            for (int r = 0; r < 4; r++) acc[mt][nt][r] = 0.f;

    const int nIter = K >> 4;

    // ---- issue helper (tile t into stage s) inlined twice below ----
#define ISSUE_TILE(t, s)                                                          \
    do {                                                                          \
        const int k0_ = (t) << 4;                                                 \
        cpasync16(asA + (unsigned)((s) * BUFW + s_r * SA + s_c) * 4u,             \
                  &A[(size_t)(m0 + s_r) * K + k0_ + s_c]);                        \
        cpasync16(asA + (unsigned)((s) * BUFW + (s_r + 64) * SA + s_c) * 4u,      \
                  &A[(size_t)(m0 + s_r + 64) * K + k0_ + s_c]);                   \
        cpasync16(asB + (unsigned)((s) * BUFW + s_r * SA + s_c) * 4u,             \
                  &Wt[(size_t)(n0 + s_r) * K + k0_ + s_c]);                       \
        cpasync16(asB + (unsigned)((s) * BUFW + (s_r + 64) * SA + s_c) * 4u,      \
                  &Wt[(size_t)(n0 + s_r + 64) * K + k0_ + s_c]);                  \
    } while (0)

    // prologue: stages 0..STAGES-2
#pragma unroll
    for (int s = 0; s < STAGES - 1; s++) {
        ISSUE_TILE(s, s);
        asm volatile("cp.async.commit_group;");
    }

    for (int it = 0; it < nIter; it++) {
        asm volatile("cp.async.wait_group %0;" :: "n"(STAGES - 2));
        __syncthreads();

        // issue next tile (or empty group to keep the count consistent)
        const int nt_ = it + STAGES - 1;
        if (nt_ < nIter) ISSUE_TILE(nt_, nt_ & (STAGES - 1));
        asm volatile("cp.async.commit_group;");

        const int buf = it & (STAGES - 1);
#pragma unroll
        for (int ks = 0; ks < 2; ks++) {
            unsigned afr[4][4];
#pragma unroll
            for (int mt = 0; mt < 4; mt++) {
                uint32_t addr = asA +
                    ((unsigned)(buf * BUFW + mt * 16 * SA + ks * 8) + aBaseW) * 4u;
                ldsm4(afr[mt][0], afr[mt][1], afr[mt][2], afr[mt][3], addr);
            }
            unsigned bfr[4][2];
#pragma unroll
            for (int p = 0; p < 2; p++) {
                uint32_t addr = asB +
                    ((unsigned)(buf * BUFW + p * 16 * SA + ks * 8) + bBaseW) * 4u;
                unsigned r0, r1, r2, r3;
                ldsm4(r0, r1, r2, r3, addr);
                bfr[2 * p][0] = r0;     bfr[2 * p][1] = r1;
                bfr[2 * p + 1][0] = r2; bfr[2 * p + 1][1] = r3;
            }
#pragma unroll
            for (int mt = 0; mt < 4; mt++)
#pragma unroll
                for (int nt2 = 0; nt2 < 4; nt2++)
                    mma_tf32(acc[mt][nt2], afr[mt], bfr[nt2]);
        }
        __syncthreads();
    }
#undef ISSUE_TILE

    // epilogue: C = acc + bias
#pragma unroll
    for (int mt = 0; mt < 4; mt++) {
        const int r = m0 + wm + mt * 16 + (lane >> 2);
#pragma unroll
        for (int nt = 0; nt < 4; nt++) {
            const int c = n0 + wn + nt * 8 + ((lane & 3) << 1);
            float2 o0 = make_float2(acc[mt][nt][0] + bias[c],
                                    acc[mt][nt][1] + bias[c + 1]);
            float2 o1 = make_float2(acc[mt][nt][2] + bias[c],
                                    acc[mt][nt][3] + bias[c + 1]);
            *(float2*)&C[(size_t)r * N + c] = o0;
            *(float2*)&C[(size_t)(r + 8) * N + c] = o1;
        }
    }
}

// ---------------------------------------------------------------------------
// One block per (window b, head h). 128 threads. Writes tf32-rounded output.
// ---------------------------------------------------------------------------
__global__ void attn_kernel(const float* __restrict__ mask,
                            const float* __restrict__ bias_table,
                            const int* __restrict__ rel_idx) {
    __shared__ float qs[SW][HD + 1];
    __shared__ float ks[SW][HD + 1];
    __shared__ float vs[SW][HD + 1];
    __shared__ float at[SW][SW];

    const int bh = blockIdx.x;
    const int b = bh / HEADS;
    const int h = bh % HEADS;
    const int tid = threadIdx.x;
    const float scale = 0.17677669529663689f;

    const float* qkv = g_qkv + (size_t)b * SW * (3 * DIMC);

    for (int e = tid; e < SW * HD; e += 128) {
        const int s = e / HD, d = e % HD;
        const size_t base = (size_t)s * (3 * DIMC) + h * HD + d;
        qs[s][d] = qkv[base] * scale;
        ks[s][d] = qkv[base + DIMC];
        vs[s][d] = qkv[base + 2 * DIMC];
    }
    __syncthreads();

    const float* mrow = mask + (size_t)(b % NWIN) * SW * SW;
    for (int e = tid; e < SW * SW; e += 128) {
        const int i = e / SW, j = e % SW;
        float acc = 0.f;
#pragma unroll
        for (int d = 0; d < HD; d++) acc += qs[i][d] * ks[j][d];
        at[i][j] = acc + bias_table[rel_idx[e] * HEADS + h] + mrow[e];
    }
    __syncthreads();

    if (tid < SW) {
        float m = -1e30f;
#pragma unroll
        for (int j = 0; j < SW; j++) m = fmaxf(m, at[tid][j]);
        float sum = 0.f;
#pragma unroll
        for (int j = 0; j < SW; j++) {
            float e2 = __expf(at[tid][j] - m);
            at[tid][j] = e2;
            sum += e2;
        }
        const float inv = 1.f / sum;
#pragma unroll
        for (int j = 0; j < SW; j++) at[tid][j] *= inv;
    }
    __syncthreads();

    float* out = g_att + (size_t)b * SW * DIMC;
    for (int e = tid; e < SW * HD; e += 128) {
        const int i = e / HD, d = e % HD;
        float acc = 0.f;
#pragma unroll
        for (int j = 0; j < SW; j++) acc += at[i][j] * vs[j][d];
        out[(size_t)i * DIMC + h * HD + d] = f2tf32f(acc);
    }
}

// ---------------------------------------------------------------------------
extern "C" void kernel_launch(void* const* d_in, const int* in_sizes, int n_in,
                              void* d_out, int out_size) {
    const float* x          = (const float*)d_in[0];
    const float* mask       = (const float*)d_in[1];
    const float* qkv_w      = (const float*)d_in[2];
    const float* qkv_b      = (const float*)d_in[3];
    const float* proj_w     = (const float*)d_in[4];
    const float* proj_b     = (const float*)d_in[5];
    const float* bias_table = (const float*)d_in[6];
    const int*   rel_idx    = (const int*)d_in[7];

    static float* qkv_ptr = nullptr;
    static float* att_ptr = nullptr;
    static float* convx_ptr = nullptr;
    static float* wtq_ptr = nullptr;
    static float* wtp_ptr = nullptr;
    if (!qkv_ptr) {
        cudaGetSymbolAddress((void**)&qkv_ptr, g_qkv);
        cudaGetSymbolAddress((void**)&att_ptr, g_att);
        cudaGetSymbolAddress((void**)&convx_ptr, g_convx);
        cudaGetSymbolAddress((void**)&wtq_ptr, g_wtq);
        cudaGetSymbolAddress((void**)&wtp_ptr, g_wtp);
        cudaFuncSetAttribute(gemm_tf32_kernel,
                             cudaFuncAttributeMaxDynamicSharedMemorySize, GEMM_SMEM);
    }

    // 0) pre-pass conversions
    {
        const int n4 = TOKENS * DIMC / 4;
        cvt_kernel<<<(n4 + 255) / 256, 256>>>((const float4*)x, (float4*)convx_ptr, n4);
        tconv_kernel<<<dim3(3 * DIMC / 32, DIMC / 32), dim3(32, 8)>>>(
            qkv_w, wtq_ptr, DIMC, 3 * DIMC);
        tconv_kernel<<<dim3(DIMC / 32, DIMC / 32), dim3(32, 8)>>>(
            proj_w, wtp_ptr, DIMC, DIMC);
    }

    // 1) QKV projection: [100352,512] x [512,1536] + b
    gemm_tf32_kernel<<<dim3(3 * DIMC / 128, TOKENS / 128), 256, GEMM_SMEM>>>(
        convx_ptr, wtq_ptr, qkv_b, qkv_ptr, TOKENS, 3 * DIMC, DIMC);

    // 2) Windowed attention per (window, head)
    attn_kernel<<<BWIN * HEADS, 128>>>(mask, bias_table, rel_idx);

    // 3) Output projection: [100352,512] x [512,512] + b -> d_out
    gemm_tf32_kernel<<<dim3(DIMC / 128, TOKENS / 128), 256, GEMM_SMEM>>>(
        att_ptr, wtp_ptr, proj_b, (float*)d_out, TOKENS, DIMC, DIMC);
}

// round 5
// speedup vs baseline: 3.0178x; 1.1318x over previous
#include <cuda_runtime.h>
#include <cstdint>

#define DIMC 512
#define HEADS 16
#define HD 32
#define SW 49
#define NWIN 64
#define BWIN 2048
#define TOKENS (BWIN * SW)   // 100352

#define SA 20                 // smem row stride in words (conflict-free, 16B-aligned: 80B)
#define BUFW (128 * SA)       // words per tile buffer per matrix
#define STAGES 4
#define GEMM_SMEM (2 * STAGES * BUFW * 4)   // bytes

// Scratch (static device globals; no runtime allocation)
__device__ float g_qkv[(size_t)TOKENS * 3 * DIMC];    // [tokens, 1536] fp32 (+bias)
__device__ float g_att[(size_t)TOKENS * DIMC];        // [tokens, 512] tf32-rounded
__device__ float g_convx[(size_t)TOKENS * DIMC];      // x, tf32-rounded
__device__ float g_wtq[(size_t)(3 * DIMC) * DIMC];    // qkv_w^T [n][k] tf32-rounded
__device__ float g_wtp[(size_t)DIMC * DIMC];          // proj_w^T [n][k] tf32-rounded

__device__ __forceinline__ unsigned f2tf32(float f) {
    unsigned u;
    asm("cvt.rna.tf32.f32 %0, %1;" : "=r"(u) : "f"(f));
    return u;
}
__device__ __forceinline__ float f2tf32f(float f) { return __uint_as_float(f2tf32(f)); }

__device__ __forceinline__ void mma_tf32(float* d, const unsigned* a, const unsigned* b) {
    asm volatile(
        "mma.sync.aligned.m16n8k8.row.col.f32.tf32.tf32.f32 "
        "{%0,%1,%2,%3}, {%4,%5,%6,%7}, {%8,%9}, {%0,%1,%2,%3};"
        : "+f"(d[0]), "+f"(d[1]), "+f"(d[2]), "+f"(d[3])
        : "r"(a[0]), "r"(a[1]), "r"(a[2]), "r"(a[3]), "r"(b[0]), "r"(b[1]));
}

__device__ __forceinline__ void ldsm4(unsigned& r0, unsigned& r1,
                                      unsigned& r2, unsigned& r3, uint32_t addr) {
    asm volatile("ldmatrix.sync.aligned.m8n8.x4.shared.b16 {%0,%1,%2,%3}, [%4];"
                 : "=r"(r0), "=r"(r1), "=r"(r2), "=r"(r3) : "r"(addr));
}

__device__ __forceinline__ void cpasync16(uint32_t dst, const void* src) {
    asm volatile("cp.async.cg.shared.global [%0], [%1], 16;" :: "r"(dst), "l"(src));
}

// ---------------------------------------------------------------------------
// Pre-pass: tf32-round a contiguous fp32 array (float4 granularity)
// ---------------------------------------------------------------------------
__global__ void cvt_kernel(const float4* __restrict__ src, float4* __restrict__ dst, int n4) {
    int i = blockIdx.x * blockDim.x + threadIdx.x;
    if (i < n4) {
        float4 v = src[i];
        dst[i] = make_float4(f2tf32f(v.x), f2tf32f(v.y), f2tf32f(v.z), f2tf32f(v.w));
    }
}

// Pre-pass: Wt[n*K + k] = tf32(W[k*N + n]);  32x32 tiles, 32x8 threads
__global__ void tconv_kernel(const float* __restrict__ W, float* __restrict__ Wt,
                             int K, int N) {
    __shared__ float t[32][33];
    const int n0 = blockIdx.x * 32, k0 = blockIdx.y * 32;
    const int tx = threadIdx.x, ty = threadIdx.y;
#pragma unroll
    for (int r = 0; r < 32; r += 8)
        t[ty + r][tx] = W[(size_t)(k0 + ty + r) * N + n0 + tx];
    __syncthreads();
#pragma unroll
    for (int r = 0; r < 32; r += 8)
        Wt[(size_t)(n0 + ty + r) * K + k0 + tx] = f2tf32f(t[tx][ty + r]);
}

// ---------------------------------------------------------------------------
// C[M,N] = A[M,K] @ Wt[N,K]^T + bias[N]   (A, Wt pre-rounded to tf32)
// Block tile 128x128x16, 256 threads, 8 warps (2m x 4n), warp tile 64x32.
// 4-stage cp.async pipeline; ONE barrier per k-tile.
// ---------------------------------------------------------------------------
__global__ __launch_bounds__(256) void gemm_tf32_kernel(
        const float* __restrict__ A, const float* __restrict__ Wt,
        const float* __restrict__ bias, float* __restrict__ C,
        int M, int N, int K) {
    extern __shared__ unsigned sh[];
    unsigned* As = sh;                       // STAGES*BUFW
    unsigned* Bs = sh + STAGES * BUFW;

    const int tid = threadIdx.x;
    const int lane = tid & 31;
    const int wid = tid >> 5;
    const int wm = (wid >> 2) * 64;
    const int wn = (wid & 3) * 32;
    const int m0 = blockIdx.y * 128;
    const int n0 = blockIdx.x * 128;

    const int s_r = tid >> 2;            // 0..63 (second op at +64)
    const int s_c = (tid & 3) << 2;      // 0,4,8,12

    const int lm = lane >> 3, lr = lane & 7;
    const unsigned aBaseW = (unsigned)((wm + ((lm & 1) << 3) + lr) * SA + ((lm >> 1) << 2));
    const unsigned bBaseW = (unsigned)((wn + ((lm >> 1) << 3) + lr) * SA + ((lm & 1) << 2));
    const uint32_t asA = (uint32_t)__cvta_generic_to_shared(As);
    const uint32_t asB = (uint32_t)__cvta_generic_to_shared(Bs);

    float acc[4][4][4];
#pragma unroll
    for (int mt = 0; mt < 4; mt++)
#pragma unroll
        for (int nt = 0; nt < 4; nt++)
#pragma unroll
            for (int r = 0; r < 4; r++) acc[mt][nt][r] = 0.f;

    const int nIter = K >> 4;

#define ISSUE_TILE(t, s)                                                          \
    do {                                                                          \
        const int k0_ = (t) << 4;                                                 \
        cpasync16(asA + (unsigned)((s) * BUFW + s_r * SA + s_c) * 4u,             \
                  &A[(size_t)(m0 + s_r) * K + k0_ + s_c]);                        \
        cpasync16(asA + (unsigned)((s) * BUFW + (s_r + 64) * SA + s_c) * 4u,      \
                  &A[(size_t)(m0 + s_r + 64) * K + k0_ + s_c]);                   \
        cpasync16(asB + (unsigned)((s) * BUFW + s_r * SA + s_c) * 4u,             \
                  &Wt[(size_t)(n0 + s_r) * K + k0_ + s_c]);                       \
        cpasync16(asB + (unsigned)((s) * BUFW + (s_r + 64) * SA + s_c) * 4u,      \
                  &Wt[(size_t)(n0 + s_r + 64) * K + k0_ + s_c]);                  \
    } while (0)

    // prologue: stages 0..STAGES-2
#pragma unroll
    for (int s = 0; s < STAGES - 1; s++) {
        ISSUE_TILE(s, s);
        asm volatile("cp.async.commit_group;");
    }

    for (int it = 0; it < nIter; it++) {
        asm volatile("cp.async.wait_group %0;" :: "n"(STAGES - 2));
        __syncthreads();

        const int nt_ = it + STAGES - 1;
        if (nt_ < nIter) ISSUE_TILE(nt_, nt_ & (STAGES - 1));
        asm volatile("cp.async.commit_group;");

        const int buf = it & (STAGES - 1);
#pragma unroll
        for (int ks = 0; ks < 2; ks++) {
            unsigned afr[4][4];
#pragma unroll
            for (int mt = 0; mt < 4; mt++) {
                uint32_t addr = asA +
                    ((unsigned)(buf * BUFW + mt * 16 * SA + ks * 8) + aBaseW) * 4u;
                ldsm4(afr[mt][0], afr[mt][1], afr[mt][2], afr[mt][3], addr);
            }
            unsigned bfr[4][2];
#pragma unroll
            for (int p = 0; p < 2; p++) {
                uint32_t addr = asB +
                    ((unsigned)(buf * BUFW + p * 16 * SA + ks * 8) + bBaseW) * 4u;
                unsigned r0, r1, r2, r3;
                ldsm4(r0, r1, r2, r3, addr);
                bfr[2 * p][0] = r0;     bfr[2 * p][1] = r1;
                bfr[2 * p + 1][0] = r2; bfr[2 * p + 1][1] = r3;
            }
#pragma unroll
            for (int mt = 0; mt < 4; mt++)
#pragma unroll
                for (int nt2 = 0; nt2 < 4; nt2++)
                    mma_tf32(acc[mt][nt2], afr[mt], bfr[nt2]);
        }
    }
#undef ISSUE_TILE

    // epilogue: C = acc + bias
#pragma unroll
    for (int mt = 0; mt < 4; mt++) {
        const int r = m0 + wm + mt * 16 + (lane >> 2);
#pragma unroll
        for (int nt = 0; nt < 4; nt++) {
            const int c = n0 + wn + nt * 8 + ((lane & 3) << 1);
            float2 o0 = make_float2(acc[mt][nt][0] + bias[c],
                                    acc[mt][nt][1] + bias[c + 1]);
            float2 o1 = make_float2(acc[mt][nt][2] + bias[c],
                                    acc[mt][nt][3] + bias[c + 1]);
            *(float2*)&C[(size_t)r * N + c] = o0;
            *(float2*)&C[(size_t)(r + 8) * N + c] = o1;
        }
    }
}

// ---------------------------------------------------------------------------
// Attention: one block per (window b, head h), 64 threads, thread i = query row.
// Q row, scores, output all in registers; K/V via broadcast float4 LDS.
// ---------------------------------------------------------------------------
#define KVP 36   // smem row stride in words (16B aligned)

__global__ __launch_bounds__(64) void attn_kernel(const float* __restrict__ mask,
                                                  const float* __restrict__ bias_table,
                                                  const int* __restrict__ rel_idx) {
    __shared__ float qs[SW][KVP];
    __shared__ float ks[SW][KVP];
    __shared__ float vs[SW][KVP];

    const int bh = blockIdx.x;
    const int b = bh / HEADS;
    const int h = bh % HEADS;
    const int tid = threadIdx.x;
    const float scale = 0.17677669529663689f;   // 32^-0.5

    const float* qkv = g_qkv + (size_t)b * SW * (3 * DIMC);
    for (int e = tid; e < SW * HD; e += 64) {
        const int s = e >> 5, d = e & 31;
        const size_t base = (size_t)s * (3 * DIMC) + h * HD + d;
        qs[s][d] = qkv[base] * scale;
        ks[s][d] = qkv[base + DIMC];
        vs[s][d] = qkv[base + 2 * DIMC];
    }
    __syncthreads();

    if (tid < SW) {
        float q[HD];
#pragma unroll
        for (int d = 0; d < HD; d++) q[d] = qs[tid][d];

        const float* mrow = mask + (size_t)(b % NWIN) * SW * SW + tid * SW;
        const int* ridx = rel_idx + tid * SW;

        float s_[SW];
        float mx = -1e30f;
#pragma unroll
        for (int j = 0; j < SW; j++) {
            const float4* kr = (const float4*)&ks[j][0];
            float a0 = 0.f, a1 = 0.f, a2 = 0.f, a3 = 0.f;
#pragma unroll
            for (int d4 = 0; d4 < 8; d4++) {
                float4 kv = kr[d4];
                a0 += q[4 * d4 + 0] * kv.x;
                a1 += q[4 * d4 + 1] * kv.y;
                a2 += q[4 * d4 + 2] * kv.z;
                a3 += q[4 * d4 + 3] * kv.w;
            }
            float acc = (a0 + a1) + (a2 + a3)
                      + bias_table[ridx[j] * HEADS + h] + mrow[j];
            s_[j] = acc;
            mx = fmaxf(mx, acc);
        }
        float sum = 0.f;
#pragma unroll
        for (int j = 0; j < SW; j++) {
            float e2 = __expf(s_[j] - mx);
            s_[j] = e2;
            sum += e2;
        }
        const float inv = 1.f / sum;

        float o[HD];
#pragma unroll
        for (int d = 0; d < HD; d++) o[d] = 0.f;
#pragma unroll
        for (int j = 0; j < SW; j++) {
            const float p = s_[j];
            const float4* vr = (const float4*)&vs[j][0];
#pragma unroll
            for (int d4 = 0; d4 < 8; d4++) {
                float4 vv = vr[d4];
                o[4 * d4 + 0] += p * vv.x;
                o[4 * d4 + 1] += p * vv.y;
                o[4 * d4 + 2] += p * vv.z;
                o[4 * d4 + 3] += p * vv.w;
            }
        }
        float* out = g_att + (size_t)b * SW * DIMC + (size_t)tid * DIMC + h * HD;
#pragma unroll
        for (int d = 0; d < HD; d++) out[d] = f2tf32f(o[d] * inv);
    }
}

// ---------------------------------------------------------------------------
extern "C" void kernel_launch(void* const* d_in, const int* in_sizes, int n_in,
                              void* d_out, int out_size) {
    const float* x          = (const float*)d_in[0];
    const float* mask       = (const float*)d_in[1];
    const float* qkv_w      = (const float*)d_in[2];
    const float* qkv_b      = (const float*)d_in[3];
    const float* proj_w     = (const float*)d_in[4];
    const float* proj_b     = (const float*)d_in[5];
    const float* bias_table = (const float*)d_in[6];
    const int*   rel_idx    = (const int*)d_in[7];

    static float* qkv_ptr = nullptr;
    static float* att_ptr = nullptr;
    static float* convx_ptr = nullptr;
    static float* wtq_ptr = nullptr;
    static float* wtp_ptr = nullptr;
    if (!qkv_ptr) {
        cudaGetSymbolAddress((void**)&qkv_ptr, g_qkv);
        cudaGetSymbolAddress((void**)&att_ptr, g_att);
        cudaGetSymbolAddress((void**)&convx_ptr, g_convx);
        cudaGetSymbolAddress((void**)&wtq_ptr, g_wtq);
        cudaGetSymbolAddress((void**)&wtp_ptr, g_wtp);
        cudaFuncSetAttribute(gemm_tf32_kernel,
                             cudaFuncAttributeMaxDynamicSharedMemorySize, GEMM_SMEM);
    }

    // 0) pre-pass conversions
    {
        const int n4 = TOKENS * DIMC / 4;
        cvt_kernel<<<(n4 + 255) / 256, 256>>>((const float4*)x, (float4*)convx_ptr, n4);
        tconv_kernel<<<dim3(3 * DIMC / 32, DIMC / 32), dim3(32, 8)>>>(
            qkv_w, wtq_ptr, DIMC, 3 * DIMC);
        tconv_kernel<<<dim3(DIMC / 32, DIMC / 32), dim3(32, 8)>>>(
            proj_w, wtp_ptr, DIMC, DIMC);
    }

    // 1) QKV projection: [100352,512] x [512,1536] + b
    gemm_tf32_kernel<<<dim3(3 * DIMC / 128, TOKENS / 128), 256, GEMM_SMEM>>>(
        convx_ptr, wtq_ptr, qkv_b, qkv_ptr, TOKENS, 3 * DIMC, DIMC);

    // 2) Windowed attention per (window, head)
    attn_kernel<<<BWIN * HEADS, 64>>>(mask, bias_table, rel_idx);

    // 3) Output projection: [100352,512] x [512,512] + b -> d_out
    gemm_tf32_kernel<<<dim3(DIMC / 128, TOKENS / 128), 256, GEMM_SMEM>>>(
        att_ptr, wtp_ptr, proj_b, (float*)d_out, TOKENS, DIMC, DIMC);
}

// round 6
// speedup vs baseline: 3.3841x; 1.1214x over previous
#include <cuda_runtime.h>
#include <cstdint>

#define DIMC 512
#define HEADS 16
#define HD 32
#define SW 49
#define NWIN 64
#define BWIN 2048
#define TOKENS (BWIN * SW)   // 100352

#define SA 20                 // smem row stride in words (conflict-free, 16B-aligned: 80B)
#define BUFW (128 * SA)       // words per tile buffer per matrix
#define STAGES 4
#define GEMM_SMEM (2 * STAGES * BUFW * 4)   // bytes

// Scratch (static device globals; no runtime allocation)
__device__ float g_qkv[(size_t)TOKENS * 3 * DIMC];    // [tokens, 1536] fp32 (+bias)
__device__ float g_att[(size_t)TOKENS * DIMC];        // [tokens, 512] tf32-rounded
__device__ float g_convx[(size_t)TOKENS * DIMC];      // x, tf32-rounded
__device__ float g_wtq[(size_t)(3 * DIMC) * DIMC];    // qkv_w^T [n][k] tf32-rounded
__device__ float g_wtp[(size_t)DIMC * DIMC];          // proj_w^T [n][k] tf32-rounded
__device__ float g_mb[(size_t)NWIN * HEADS * SW * SW]; // fused mask+bias [w][h][i][j]

__device__ __forceinline__ unsigned f2tf32(float f) {
    unsigned u;
    asm("cvt.rna.tf32.f32 %0, %1;" : "=r"(u) : "f"(f));
    return u;
}
__device__ __forceinline__ float f2tf32f(float f) { return __uint_as_float(f2tf32(f)); }

__device__ __forceinline__ void mma_tf32(float* d, const unsigned* a, const unsigned* b) {
    asm volatile(
        "mma.sync.aligned.m16n8k8.row.col.f32.tf32.tf32.f32 "
        "{%0,%1,%2,%3}, {%4,%5,%6,%7}, {%8,%9}, {%0,%1,%2,%3};"
        : "+f"(d[0]), "+f"(d[1]), "+f"(d[2]), "+f"(d[3])
        : "r"(a[0]), "r"(a[1]), "r"(a[2]), "r"(a[3]), "r"(b[0]), "r"(b[1]));
}

__device__ __forceinline__ void ldsm4(unsigned& r0, unsigned& r1,
                                      unsigned& r2, unsigned& r3, uint32_t addr) {
    asm volatile("ldmatrix.sync.aligned.m8n8.x4.shared.b16 {%0,%1,%2,%3}, [%4];"
                 : "=r"(r0), "=r"(r1), "=r"(r2), "=r"(r3) : "r"(addr));
}

__device__ __forceinline__ void cpasync16(uint32_t dst, const void* src) {
    asm volatile("cp.async.cg.shared.global [%0], [%1], 16;" :: "r"(dst), "l"(src));
}

// ---------------------------------------------------------------------------
// Pre-pass: tf32-round a contiguous fp32 array (float4 granularity)
// ---------------------------------------------------------------------------
__global__ void cvt_kernel(const float4* __restrict__ src, float4* __restrict__ dst, int n4) {
    int i = blockIdx.x * blockDim.x + threadIdx.x;
    if (i < n4) {
        float4 v = src[i];
        dst[i] = make_float4(f2tf32f(v.x), f2tf32f(v.y), f2tf32f(v.z), f2tf32f(v.w));
    }
}

// Pre-pass: Wt[n*K + k] = tf32(W[k*N + n]);  32x32 tiles, 32x8 threads
__global__ void tconv_kernel(const float* __restrict__ W, float* __restrict__ Wt,
                             int K, int N) {
    __shared__ float t[32][33];
    const int n0 = blockIdx.x * 32, k0 = blockIdx.y * 32;
    const int tx = threadIdx.x, ty = threadIdx.y;
#pragma unroll
    for (int r = 0; r < 32; r += 8)
        t[ty + r][tx] = W[(size_t)(k0 + ty + r) * N + n0 + tx];
    __syncthreads();
#pragma unroll
    for (int r = 0; r < 32; r += 8)
        Wt[(size_t)(n0 + ty + r) * K + k0 + tx] = f2tf32f(t[tx][ty + r]);
}

// Pre-pass: fused mask+bias  mb[w][h][e] = mask[w][e] + bias_table[rel_idx[e]][h]
__global__ void mb_kernel(const float* __restrict__ mask,
                          const float* __restrict__ bias_table,
                          const int* __restrict__ rel_idx) {
    const int wh = blockIdx.x;
    const int w = wh / HEADS, h = wh % HEADS;
    const float* mrow = mask + (size_t)w * SW * SW;
    float* out = g_mb + (size_t)wh * SW * SW;
    for (int e = threadIdx.x; e < SW * SW; e += blockDim.x)
        out[e] = mrow[e] + bias_table[rel_idx[e] * HEADS + h];
}

// ---------------------------------------------------------------------------
// C[M,N] = A[M,K] @ Wt[N,K]^T + bias[N]   (A, Wt pre-rounded to tf32)
// Block tile 128x128x16, 256 threads, 8 warps (2m x 4n), warp tile 64x32.
// 4-stage cp.async pipeline; 2 CTAs/SM forced via launch bounds.
// ---------------------------------------------------------------------------
__global__ __launch_bounds__(256, 2) void gemm_tf32_kernel(
        const float* __restrict__ A, const float* __restrict__ Wt,
        const float* __restrict__ bias, float* __restrict__ C,
        int M, int N, int K) {
    extern __shared__ unsigned sh[];
    unsigned* As = sh;                       // STAGES*BUFW
    unsigned* Bs = sh + STAGES * BUFW;

    const int tid = threadIdx.x;
    const int lane = tid & 31;
    const int wid = tid >> 5;
    const int wm = (wid >> 2) * 64;
    const int wn = (wid & 3) * 32;
    const int m0 = blockIdx.y * 128;
    const int n0 = blockIdx.x * 128;

    const int s_r = tid >> 2;            // 0..63 (second op at +64)
    const int s_c = (tid & 3) << 2;      // 0,4,8,12

    const int lm = lane >> 3, lr = lane & 7;
    const unsigned aBaseW = (unsigned)((wm + ((lm & 1) << 3) + lr) * SA + ((lm >> 1) << 2));
    const unsigned bBaseW = (unsigned)((wn + ((lm >> 1) << 3) + lr) * SA + ((lm & 1) << 2));
    const uint32_t asA = (uint32_t)__cvta_generic_to_shared(As);
    const uint32_t asB = (uint32_t)__cvta_generic_to_shared(Bs);

    float acc[4][4][4];
#pragma unroll
    for (int mt = 0; mt < 4; mt++)
#pragma unroll
        for (int nt = 0; nt < 4; nt++)
#pragma unroll
            for (int r = 0; r < 4; r++) acc[mt][nt][r] = 0.f;

    const int nIter = K >> 4;

#define ISSUE_TILE(t, s)                                                          \
    do {                                                                          \
        const int k0_ = (t) << 4;                                                 \
        cpasync16(asA + (unsigned)((s) * BUFW + s_r * SA + s_c) * 4u,             \
                  &A[(size_t)(m0 + s_r) * K + k0_ + s_c]);                        \
        cpasync16(asA + (unsigned)((s) * BUFW + (s_r + 64) * SA + s_c) * 4u,      \
                  &A[(size_t)(m0 + s_r + 64) * K + k0_ + s_c]);                   \
        cpasync16(asB + (unsigned)((s) * BUFW + s_r * SA + s_c) * 4u,             \
                  &Wt[(size_t)(n0 + s_r) * K + k0_ + s_c]);                       \
        cpasync16(asB + (unsigned)((s) * BUFW + (s_r + 64) * SA + s_c) * 4u,      \
                  &Wt[(size_t)(n0 + s_r + 64) * K + k0_ + s_c]);                  \
    } while (0)

    // prologue: stages 0..STAGES-2
#pragma unroll
    for (int s = 0; s < STAGES - 1; s++) {
        ISSUE_TILE(s, s);
        asm volatile("cp.async.commit_group;");
    }

    for (int it = 0; it < nIter; it++) {
        asm volatile("cp.async.wait_group %0;" :: "n"(STAGES - 2));
        __syncthreads();

        const int nt_ = it + STAGES - 1;
        if (nt_ < nIter) ISSUE_TILE(nt_, nt_ & (STAGES - 1));
        asm volatile("cp.async.commit_group;");

        const int buf = it & (STAGES - 1);
#pragma unroll
        for (int ks = 0; ks < 2; ks++) {
            unsigned afr[4][4];
#pragma unroll
            for (int mt = 0; mt < 4; mt++) {
                uint32_t addr = asA +
                    ((unsigned)(buf * BUFW + mt * 16 * SA + ks * 8) + aBaseW) * 4u;
                ldsm4(afr[mt][0], afr[mt][1], afr[mt][2], afr[mt][3], addr);
            }
            unsigned bfr[4][2];
#pragma unroll
            for (int p = 0; p < 2; p++) {
                uint32_t addr = asB +
                    ((unsigned)(buf * BUFW + p * 16 * SA + ks * 8) + bBaseW) * 4u;
                unsigned r0, r1, r2, r3;
                ldsm4(r0, r1, r2, r3, addr);
                bfr[2 * p][0] = r0;     bfr[2 * p][1] = r1;
                bfr[2 * p + 1][0] = r2; bfr[2 * p + 1][1] = r3;
            }
#pragma unroll
            for (int mt = 0; mt < 4; mt++)
#pragma unroll
                for (int nt2 = 0; nt2 < 4; nt2++)
                    mma_tf32(acc[mt][nt2], afr[mt], bfr[nt2]);
        }
    }
#undef ISSUE_TILE

    // epilogue: C = acc + bias
#pragma unroll
    for (int mt = 0; mt < 4; mt++) {
        const int r = m0 + wm + mt * 16 + (lane >> 2);
#pragma unroll
        for (int nt = 0; nt < 4; nt++) {
            const int c = n0 + wn + nt * 8 + ((lane & 3) << 1);
            float2 o0 = make_float2(acc[mt][nt][0] + bias[c],
                                    acc[mt][nt][1] + bias[c + 1]);
            float2 o1 = make_float2(acc[mt][nt][2] + bias[c],
                                    acc[mt][nt][3] + bias[c + 1]);
            *(float2*)&C[(size_t)r * N + c] = o0;
            *(float2*)&C[(size_t)(r + 8) * N + c] = o1;
        }
    }
}

// ---------------------------------------------------------------------------
// Attention: one block per (window b, head h), 64 threads, thread i = query row.
// Fused mask+bias from g_mb (contiguous); K/V via broadcast float4 LDS.
// ---------------------------------------------------------------------------
#define KVP 36   // smem row stride in words (16B aligned)

__global__ __launch_bounds__(64) void attn_kernel() {
    __shared__ float qs[SW][KVP];
    __shared__ float ks[SW][KVP];
    __shared__ float vs[SW][KVP];

    const int bh = blockIdx.x;
    const int b = bh / HEADS;
    const int h = bh % HEADS;
    const int tid = threadIdx.x;
    const float scale = 0.17677669529663689f;   // 32^-0.5

    const float* qkv = g_qkv + (size_t)b * SW * (3 * DIMC);
    for (int e = tid; e < SW * HD; e += 64) {
        const int s = e >> 5, d = e & 31;
        const size_t base = (size_t)s * (3 * DIMC) + h * HD + d;
        qs[s][d] = qkv[base] * scale;
        ks[s][d] = qkv[base + DIMC];
        vs[s][d] = qkv[base + 2 * DIMC];
    }
    __syncthreads();

    if (tid < SW) {
        float q[HD];
#pragma unroll
        for (int d = 0; d < HD; d++) q[d] = qs[tid][d];

        const float* mrow = g_mb +
            ((size_t)((b % NWIN) * HEADS + h) * SW + tid) * SW;

        float s_[SW];
        float mx = -1e30f;
#pragma unroll
        for (int j = 0; j < SW; j++) {
            const float4* kr = (const float4*)&ks[j][0];
            float a0 = 0.f, a1 = 0.f, a2 = 0.f, a3 = 0.f;
#pragma unroll
            for (int d4 = 0; d4 < 8; d4++) {
                float4 kv = kr[d4];
                a0 += q[4 * d4 + 0] * kv.x;
                a1 += q[4 * d4 + 1] * kv.y;
                a2 += q[4 * d4 + 2] * kv.z;
                a3 += q[4 * d4 + 3] * kv.w;
            }
            float acc = (a0 + a1) + (a2 + a3) + mrow[j];
            s_[j] = acc;
            mx = fmaxf(mx, acc);
        }
        float sum = 0.f;
#pragma unroll
        for (int j = 0; j < SW; j++) {
            float e2 = __expf(s_[j] - mx);
            s_[j] = e2;
            sum += e2;
        }
        const float inv = 1.f / sum;

        float o[HD];
#pragma unroll
        for (int d = 0; d < HD; d++) o[d] = 0.f;
#pragma unroll
        for (int j = 0; j < SW; j++) {
            const float p = s_[j];
            const float4* vr = (const float4*)&vs[j][0];
#pragma unroll
            for (int d4 = 0; d4 < 8; d4++) {
                float4 vv = vr[d4];
                o[4 * d4 + 0] += p * vv.x;
                o[4 * d4 + 1] += p * vv.y;
                o[4 * d4 + 2] += p * vv.z;
                o[4 * d4 + 3] += p * vv.w;
            }
        }
        float* out = g_att + (size_t)b * SW * DIMC + (size_t)tid * DIMC + h * HD;
#pragma unroll
        for (int d = 0; d < HD; d++) out[d] = f2tf32f(o[d] * inv);
    }
}

// ---------------------------------------------------------------------------
extern "C" void kernel_launch(void* const* d_in, const int* in_sizes, int n_in,
                              void* d_out, int out_size) {
    const float* x          = (const float*)d_in[0];
    const float* mask       = (const float*)d_in[1];
    const float* qkv_w      = (const float*)d_in[2];
    const float* qkv_b      = (const float*)d_in[3];
    const float* proj_w     = (const float*)d_in[4];
    const float* proj_b     = (const float*)d_in[5];
    const float* bias_table = (const float*)d_in[6];
    const int*   rel_idx    = (const int*)d_in[7];

    static float* qkv_ptr = nullptr;
    static float* att_ptr = nullptr;
    static float* convx_ptr = nullptr;
    static float* wtq_ptr = nullptr;
    static float* wtp_ptr = nullptr;
    if (!qkv_ptr) {
        cudaGetSymbolAddress((void**)&qkv_ptr, g_qkv);
        cudaGetSymbolAddress((void**)&att_ptr, g_att);
        cudaGetSymbolAddress((void**)&convx_ptr, g_convx);
        cudaGetSymbolAddress((void**)&wtq_ptr, g_wtq);
        cudaGetSymbolAddress((void**)&wtp_ptr, g_wtp);
        cudaFuncSetAttribute(gemm_tf32_kernel,
                             cudaFuncAttributeMaxDynamicSharedMemorySize, GEMM_SMEM);
    }

    // 0) pre-pass conversions
    {
        const int n4 = TOKENS * DIMC / 4;
        cvt_kernel<<<(n4 + 255) / 256, 256>>>((const float4*)x, (float4*)convx_ptr, n4);
        tconv_kernel<<<dim3(3 * DIMC / 32, DIMC / 32), dim3(32, 8)>>>(
            qkv_w, wtq_ptr, DIMC, 3 * DIMC);
        tconv_kernel<<<dim3(DIMC / 32, DIMC / 32), dim3(32, 8)>>>(
            proj_w, wtp_ptr, DIMC, DIMC);
        mb_kernel<<<NWIN * HEADS, 256>>>(mask, bias_table, rel_idx);
    }

    // 1) QKV projection: [100352,512] x [512,1536] + b
    gemm_tf32_kernel<<<dim3(3 * DIMC / 128, TOKENS / 128), 256, GEMM_SMEM>>>(
        convx_ptr, wtq_ptr, qkv_b, qkv_ptr, TOKENS, 3 * DIMC, DIMC);

    // 2) Windowed attention per (window, head)
    attn_kernel<<<BWIN * HEADS, 64>>>();

    // 3) Output projection: [100352,512] x [512,512] + b -> d_out
    gemm_tf32_kernel<<<dim3(DIMC / 128, TOKENS / 128), 256, GEMM_SMEM>>>(
        att_ptr, wtp_ptr, proj_b, (float*)d_out, TOKENS, DIMC, DIMC);
}

// round 8
// speedup vs baseline: 4.8460x; 1.4320x over previous
#include <cuda_runtime.h>
#include <cuda_fp16.h>
#include <cstdint>

#define DIMC 512
#define HEADS 16
#define HD 32
#define SW 49
#define NWIN 64
#define BWIN 2048
#define TOKENS (BWIN * SW)   // 100352

#define SAH 40                 // smem row stride in halfs (80B: conflict-free, 16B-mult)
#define BUFH (128 * SAH)       // halfs per tile buffer per matrix (10240 B)
#define STAGES 4
#define GEMM_SMEM (2 * STAGES * BUFH * 2)   // bytes = 81920

// Scratch (static device globals; no runtime allocation)
__device__ float  g_qkv[(size_t)TOKENS * 3 * DIMC];    // [tokens, 1536] fp32 (+bias)
__device__ __half g_atth[(size_t)TOKENS * DIMC];       // attention out, fp16
__device__ __half g_xh[(size_t)TOKENS * DIMC];         // x, fp16
__device__ __half g_wtqh[(size_t)(3 * DIMC) * DIMC];   // qkv_w^T [n][k] fp16
__device__ __half g_wtph[(size_t)DIMC * DIMC];         // proj_w^T [n][k] fp16
__device__ float  g_mb[(size_t)NWIN * HEADS * SW * SW]; // fused mask+bias [w][h][i][j]

// ---------------------------------------------------------------------------
__device__ __forceinline__ void mma_f16(float* d, const unsigned* a, const unsigned* b) {
    asm volatile(
        "mma.sync.aligned.m16n8k16.row.col.f32.f16.f16.f32 "
        "{%0,%1,%2,%3}, {%4,%5,%6,%7}, {%8,%9}, {%0,%1,%2,%3};"
        : "+f"(d[0]), "+f"(d[1]), "+f"(d[2]), "+f"(d[3])
        : "r"(a[0]), "r"(a[1]), "r"(a[2]), "r"(a[3]), "r"(b[0]), "r"(b[1]));
}

__device__ __forceinline__ void ldsm4(unsigned& r0, unsigned& r1,
                                      unsigned& r2, unsigned& r3, uint32_t addr) {
    asm volatile("ldmatrix.sync.aligned.m8n8.x4.shared.b16 {%0,%1,%2,%3}, [%4];"
                 : "=r"(r0), "=r"(r1), "=r"(r2), "=r"(r3) : "r"(addr));
}

__device__ __forceinline__ void cpasync16(uint32_t dst, const void* src) {
    asm volatile("cp.async.cg.shared.global [%0], [%1], 16;" :: "r"(dst), "l"(src));
}

// ---------------------------------------------------------------------------
// Pre-pass: fp32 -> fp16 (4 elements/thread)
// ---------------------------------------------------------------------------
__global__ void cvt_h_kernel(const float4* __restrict__ src,
                             __half2* __restrict__ dst, int n4) {
    int i = blockIdx.x * blockDim.x + threadIdx.x;
    if (i < n4) {
        float4 v = src[i];
        dst[2 * i]     = __floats2half2_rn(v.x, v.y);
        dst[2 * i + 1] = __floats2half2_rn(v.z, v.w);
    }
}

// Pre-pass: Wt[n*K + k] = fp16(W[k*N + n]);  32x32 tiles, 32x8 threads
__global__ void tconv_h_kernel(const float* __restrict__ W, __half* __restrict__ Wt,
                               int K, int N) {
    __shared__ float t[32][33];
    const int n0 = blockIdx.x * 32, k0 = blockIdx.y * 32;
    const int tx = threadIdx.x, ty = threadIdx.y;
#pragma unroll
    for (int r = 0; r < 32; r += 8)
        t[ty + r][tx] = W[(size_t)(k0 + ty + r) * N + n0 + tx];
    __syncthreads();
#pragma unroll
    for (int r = 0; r < 32; r += 8)
        Wt[(size_t)(n0 + ty + r) * K + k0 + tx] = __float2half_rn(t[tx][ty + r]);
}

// Pre-pass: fused mask+bias  mb[w][h][e] = mask[w][e] + bias_table[rel_idx[e]][h]
__global__ void mb_kernel(const float* __restrict__ mask,
                          const float* __restrict__ bias_table,
                          const int* __restrict__ rel_idx) {
    const int wh = blockIdx.x;
    const int w = wh / HEADS, h = wh % HEADS;
    const float* mrow = mask + (size_t)w * SW * SW;
    float* out = g_mb + (size_t)wh * SW * SW;
    for (int e = threadIdx.x; e < SW * SW; e += blockDim.x)
        out[e] = mrow[e] + bias_table[rel_idx[e] * HEADS + h];
}

// ---------------------------------------------------------------------------
// C[M,N] = A[M,K] @ Wt[N,K]^T + bias[N]   (A, Wt fp16; fp32 accumulate)
// Block tile 128x128, k-tile 32, 256 threads, 8 warps (2m x 4n), warp 64x32.
// 4-stage cp.async pipeline; ldmatrix.x4 fragment loads.
// ---------------------------------------------------------------------------
__global__ __launch_bounds__(256, 2) void gemm_f16_kernel(
        const __half* __restrict__ A, const __half* __restrict__ Wt,
        const float* __restrict__ bias, float* __restrict__ C,
        int M, int N, int K) {
    extern __shared__ __half sh[];
    __half* As = sh;                          // STAGES*BUFH
    __half* Bs = sh + STAGES * BUFH;

    const int tid = threadIdx.x;
    const int lane = tid & 31;
    const int wid = tid >> 5;
    const int wm = (wid >> 2) * 64;
    const int wn = (wid & 3) * 32;
    const int m0 = blockIdx.y * 128;
    const int n0 = blockIdx.x * 128;

    // staging: 128 rows x 32 halfs (64B) per matrix; 2 x 16B per thread per matrix
    // idx = tid + i*256 ; row = idx>>2, seg = idx&3 (16B = 8 halfs per seg)
    const uint32_t asA = (uint32_t)__cvta_generic_to_shared(As);
    const uint32_t asB = (uint32_t)__cvta_generic_to_shared(Bs);

    // ldmatrix lane bases
    const int rowoff = ((lane >> 3) & 1) * 8 + (lane & 7);  // 0..15
    const int khalf = (lane >> 4) * 8;                      // 0 or 8 (halfs)
    const unsigned aBaseH = (unsigned)((wm + rowoff) * SAH + khalf);
    const unsigned bBaseH = (unsigned)((wn + ((lane >> 4) & 1) * 8 + (lane & 7)) * SAH
                                       + ((lane >> 3) & 1) * 8);

    float acc[4][4][4];
#pragma unroll
    for (int mt = 0; mt < 4; mt++)
#pragma unroll
        for (int nt = 0; nt < 4; nt++)
#pragma unroll
            for (int r = 0; r < 4; r++) acc[mt][nt][r] = 0.f;

    const int nIter = K >> 5;   // k-tiles of 32

#define ISSUE_TILE(t, s)                                                           \
    do {                                                                           \
        const int k0_ = (t) << 5;                                                  \
        _Pragma("unroll")                                                          \
        for (int i = 0; i < 2; i++) {                                              \
            const int idx = tid + i * 256;                                         \
            const int row = idx >> 2, seg = idx & 3;                               \
            const uint32_t doff = (uint32_t)((s) * BUFH + row * SAH + seg * 8) * 2u; \
            cpasync16(asA + doff, &A[(size_t)(m0 + row) * K + k0_ + seg * 8]);     \
            cpasync16(asB + doff, &Wt[(size_t)(n0 + row) * K + k0_ + seg * 8]);    \
        }                                                                          \
        asm volatile("cp.async.commit_group;");                                    \
    } while (0)

    // prologue: stages 0..STAGES-2
#pragma unroll
    for (int s = 0; s < STAGES - 1; s++) ISSUE_TILE(s, s);

    for (int it = 0; it < nIter; it++) {
        asm volatile("cp.async.wait_group %0;" :: "n"(STAGES - 2));
        __syncthreads();

        const int nt_ = it + STAGES - 1;
        if (nt_ < nIter) ISSUE_TILE(nt_, nt_ & (STAGES - 1));
        else asm volatile("cp.async.commit_group;");

        const int buf = it & (STAGES - 1);
#pragma unroll
        for (int ks = 0; ks < 2; ks++) {
            unsigned afr[4][4];
#pragma unroll
            for (int mt = 0; mt < 4; mt++) {
                uint32_t addr = asA +
                    ((unsigned)(buf * BUFH + mt * 16 * SAH + ks * 16) + aBaseH) * 2u;
                ldsm4(afr[mt][0], afr[mt][1], afr[mt][2], afr[mt][3], addr);
            }
            unsigned bfr[4][2];
#pragma unroll
            for (int p = 0; p < 2; p++) {
                uint32_t addr = asB +
                    ((unsigned)(buf * BUFH + p * 16 * SAH + ks * 16) + bBaseH) * 2u;
                unsigned r0, r1, r2, r3;
                ldsm4(r0, r1, r2, r3, addr);
                bfr[2 * p][0] = r0;     bfr[2 * p][1] = r1;
                bfr[2 * p + 1][0] = r2; bfr[2 * p + 1][1] = r3;
            }
#pragma unroll
            for (int mt = 0; mt < 4; mt++)
#pragma unroll
                for (int nt2 = 0; nt2 < 4; nt2++)
                    mma_f16(acc[mt][nt2], afr[mt], bfr[nt2]);
        }
    }
#undef ISSUE_TILE

    // epilogue: C = acc + bias (same fragment layout as m16n8k8)
#pragma unroll
    for (int mt = 0; mt < 4; mt++) {
        const int r = m0 + wm + mt * 16 + (lane >> 2);
#pragma unroll
        for (int nt = 0; nt < 4; nt++) {
            const int c = n0 + wn + nt * 8 + ((lane & 3) << 1);
            float2 o0 = make_float2(acc[mt][nt][0] + bias[c],
                                    acc[mt][nt][1] + bias[c + 1]);
            float2 o1 = make_float2(acc[mt][nt][2] + bias[c],
                                    acc[mt][nt][3] + bias[c + 1]);
            *(float2*)&C[(size_t)r * N + c] = o0;
            *(float2*)&C[(size_t)(r + 8) * N + c] = o1;
        }
    }
}

// ---------------------------------------------------------------------------
// Attention: one block per (window b, head h), 64 threads, thread i = query row.
// Output written as fp16 (input to proj GEMM).
// ---------------------------------------------------------------------------
#define KVP 36   // smem row stride in words (16B aligned)

__global__ __launch_bounds__(64) void attn_kernel() {
    __shared__ float qs[SW][KVP];
    __shared__ float ks[SW][KVP];
    __shared__ float vs[SW][KVP];

    const int bh = blockIdx.x;
    const int b = bh / HEADS;
    const int h = bh % HEADS;
    const int tid = threadIdx.x;
    const float scale = 0.17677669529663689f;   // 32^-0.5

    const float* qkv = g_qkv + (size_t)b * SW * (3 * DIMC);
    for (int e = tid; e < SW * HD; e += 64) {
        const int s = e >> 5, d = e & 31;
        const size_t base = (size_t)s * (3 * DIMC) + h * HD + d;
        qs[s][d] = qkv[base] * scale;
        ks[s][d] = qkv[base + DIMC];
        vs[s][d] = qkv[base + 2 * DIMC];
    }
    __syncthreads();

    if (tid < SW) {
        float q[HD];
#pragma unroll
        for (int d = 0; d < HD; d++) q[d] = qs[tid][d];

        const float* mrow = g_mb +
            ((size_t)((b % NWIN) * HEADS + h) * SW + tid) * SW;

        float s_[SW];
        float mx = -1e30f;
#pragma unroll
        for (int j = 0; j < SW; j++) {
            const float4* kr = (const float4*)&ks[j][0];
            float a0 = 0.f, a1 = 0.f, a2 = 0.f, a3 = 0.f;
#pragma unroll
            for (int d4 = 0; d4 < 8; d4++) {
                float4 kv = kr[d4];
                a0 += q[4 * d4 + 0] * kv.x;
                a1 += q[4 * d4 + 1] * kv.y;
                a2 += q[4 * d4 + 2] * kv.z;
                a3 += q[4 * d4 + 3] * kv.w;
            }
            float acc = (a0 + a1) + (a2 + a3) + mrow[j];
            s_[j] = acc;
            mx = fmaxf(mx, acc);
        }
        float sum = 0.f;
#pragma unroll
        for (int j = 0; j < SW; j++) {
            float e2 = __expf(s_[j] - mx);
            s_[j] = e2;
            sum += e2;
        }
        const float inv = 1.f / sum;

        float o[HD];
#pragma unroll
        for (int d = 0; d < HD; d++) o[d] = 0.f;
#pragma unroll
        for (int j = 0; j < SW; j++) {
            const float p = s_[j];
            const float4* vr = (const float4*)&vs[j][0];
#pragma unroll
            for (int d4 = 0; d4 < 8; d4++) {
                float4 vv = vr[d4];
                o[4 * d4 + 0] += p * vv.x;
                o[4 * d4 + 1] += p * vv.y;
                o[4 * d4 + 2] += p * vv.z;
                o[4 * d4 + 3] += p * vv.w;
            }
        }
        __half2* out = (__half2*)(g_atth + (size_t)b * SW * DIMC +
                                  (size_t)tid * DIMC + h * HD);
#pragma unroll
        for (int d = 0; d < HD; d += 2)
            out[d >> 1] = __floats2half2_rn(o[d] * inv, o[d + 1] * inv);
    }
}

// ---------------------------------------------------------------------------
extern "C" void kernel_launch(void* const* d_in, const int* in_sizes, int n_in,
                              void* d_out, int out_size) {
    const float* x          = (const float*)d_in[0];
    const float* mask       = (const float*)d_in[1];
    const float* qkv_w      = (const float*)d_in[2];
    const float* qkv_b      = (const float*)d_in[3];
    const float* proj_w     = (const float*)d_in[4];
    const float* proj_b     = (const float*)d_in[5];
    const float* bias_table = (const float*)d_in[6];
    const int*   rel_idx    = (const int*)d_in[7];

    static float*  qkv_ptr = nullptr;
    static __half* atth_ptr = nullptr;
    static __half* xh_ptr = nullptr;
    static __half* wtqh_ptr = nullptr;
    static __half* wtph_ptr = nullptr;
    if (!qkv_ptr) {
        cudaGetSymbolAddress((void**)&qkv_ptr, g_qkv);
        cudaGetSymbolAddress((void**)&atth_ptr, g_atth);
        cudaGetSymbolAddress((void**)&xh_ptr, g_xh);
        cudaGetSymbolAddress((void**)&wtqh_ptr, g_wtqh);
        cudaGetSymbolAddress((void**)&wtph_ptr, g_wtph);
        cudaFuncSetAttribute(gemm_f16_kernel,
                             cudaFuncAttributeMaxDynamicSharedMemorySize, GEMM_SMEM);
    }

    // 0) pre-pass conversions
    {
        const int n4 = TOKENS * DIMC / 4;
        cvt_h_kernel<<<(n4 + 255) / 256, 256>>>((const float4*)x, (__half2*)xh_ptr, n4);
        tconv_h_kernel<<<dim3(3 * DIMC / 32, DIMC / 32), dim3(32, 8)>>>(
            qkv_w, wtqh_ptr, DIMC, 3 * DIMC);
        tconv_h_kernel<<<dim3(DIMC / 32, DIMC / 32), dim3(32, 8)>>>(
            proj_w, wtph_ptr, DIMC, DIMC);
        mb_kernel<<<NWIN * HEADS, 256>>>(mask, bias_table, rel_idx);
    }

    // 1) QKV projection: [100352,512] x [512,1536] + b
    gemm_f16_kernel<<<dim3(3 * DIMC / 128, TOKENS / 128), 256, GEMM_SMEM>>>(
        xh_ptr, wtqh_ptr, qkv_b, qkv_ptr, TOKENS, 3 * DIMC, DIMC);

    // 2) Windowed attention per (window, head)
    attn_kernel<<<BWIN * HEADS, 64>>>();

    // 3) Output projection: [100352,512] x [512,512] + b -> d_out
    gemm_f16_kernel<<<dim3(DIMC / 128, TOKENS / 128), 256, GEMM_SMEM>>>(
        atth_ptr, wtph_ptr, proj_b, (float*)d_out, TOKENS, DIMC, DIMC);
}

// round 9
// speedup vs baseline: 6.9555x; 1.4353x over previous
#include <cuda_runtime.h>
#include <cuda_fp16.h>
#include <cstdint>

#define DIMC 512
#define HEADS 16
#define HD 32
#define SW 49
#define NWIN 64
#define BWIN 2048
#define TOKENS (BWIN * SW)   // 100352

#define SAH 40                 // smem row stride in halfs (80B: conflict-free, 16B-mult)
#define BUFH (128 * SAH)       // halfs per tile buffer per matrix
#define STAGES 4
#define GEMM_SMEM (2 * STAGES * BUFH * 2)   // bytes = 81920

// Scratch (static device globals; no runtime allocation)
__device__ __half g_qkvh[(size_t)TOKENS * 3 * DIMC];   // qkv out, fp16
__device__ __half g_atth[(size_t)TOKENS * DIMC];       // attention out, fp16
__device__ __half g_xh[(size_t)TOKENS * DIMC];         // x, fp16
__device__ __half g_wtqh[(size_t)(3 * DIMC) * DIMC];   // qkv_w^T [n][k] fp16
__device__ __half g_wtph[(size_t)DIMC * DIMC];         // proj_w^T [n][k] fp16
__device__ float  g_mb[(size_t)NWIN * HEADS * SW * SW + 256]; // fused mask+bias (+pad)

// ---------------------------------------------------------------------------
__device__ __forceinline__ void mma_f16(float* d, const unsigned* a, const unsigned* b) {
    asm volatile(
        "mma.sync.aligned.m16n8k16.row.col.f32.f16.f16.f32 "
        "{%0,%1,%2,%3}, {%4,%5,%6,%7}, {%8,%9}, {%0,%1,%2,%3};"
        : "+f"(d[0]), "+f"(d[1]), "+f"(d[2]), "+f"(d[3])
        : "r"(a[0]), "r"(a[1]), "r"(a[2]), "r"(a[3]), "r"(b[0]), "r"(b[1]));
}

__device__ __forceinline__ void ldsm4(unsigned& r0, unsigned& r1,
                                      unsigned& r2, unsigned& r3, uint32_t addr) {
    asm volatile("ldmatrix.sync.aligned.m8n8.x4.shared.b16 {%0,%1,%2,%3}, [%4];"
                 : "=r"(r0), "=r"(r1), "=r"(r2), "=r"(r3) : "r"(addr));
}

__device__ __forceinline__ void ldsm4t(unsigned& r0, unsigned& r1,
                                       unsigned& r2, unsigned& r3, uint32_t addr) {
    asm volatile("ldmatrix.sync.aligned.m8n8.x4.trans.shared.b16 {%0,%1,%2,%3}, [%4];"
                 : "=r"(r0), "=r"(r1), "=r"(r2), "=r"(r3) : "r"(addr));
}

__device__ __forceinline__ void cpasync16(uint32_t dst, const void* src) {
    asm volatile("cp.async.cg.shared.global [%0], [%1], 16;" :: "r"(dst), "l"(src));
}

__device__ __forceinline__ unsigned packh2(float lo, float hi) {
    __half2 t = __floats2half2_rn(lo, hi);
    return *(unsigned*)&t;
}

// exp on the FMA/ALU pipes (no MUFU): 2^(z*log2e), |rel err| ~2.4e-6
__device__ __forceinline__ float fast_exp(float z) {
    z = fmaxf(z, -80.f);
    float y = z * 1.44269504088896f;
    int i = __float2int_rn(y);
    float f = y - (float)i;
    float p = 0.0013333558146f;
    p = fmaf(p, f, 0.0096181291076f);
    p = fmaf(p, f, 0.0555041086648f);
    p = fmaf(p, f, 0.2402265069591f);
    p = fmaf(p, f, 0.6931471805599f);
    p = fmaf(p, f, 1.0f);
    return p * __int_as_float((i + 127) << 23);
}

// ---------------------------------------------------------------------------
// Pre-pass kernels
// ---------------------------------------------------------------------------
__global__ void cvt_h_kernel(const float4* __restrict__ src,
                             __half2* __restrict__ dst, int n4) {
    int i = blockIdx.x * blockDim.x + threadIdx.x;
    if (i < n4) {
        float4 v = src[i];
        dst[2 * i]     = __floats2half2_rn(v.x, v.y);
        dst[2 * i + 1] = __floats2half2_rn(v.z, v.w);
    }
}

__global__ void tconv_h_kernel(const float* __restrict__ W, __half* __restrict__ Wt,
                               int K, int N) {
    __shared__ float t[32][33];
    const int n0 = blockIdx.x * 32, k0 = blockIdx.y * 32;
    const int tx = threadIdx.x, ty = threadIdx.y;
#pragma unroll
    for (int r = 0; r < 32; r += 8)
        t[ty + r][tx] = W[(size_t)(k0 + ty + r) * N + n0 + tx];
    __syncthreads();
#pragma unroll
    for (int r = 0; r < 32; r += 8)
        Wt[(size_t)(n0 + ty + r) * K + k0 + tx] = __float2half_rn(t[tx][ty + r]);
}

__global__ void mb_kernel(const float* __restrict__ mask,
                          const float* __restrict__ bias_table,
                          const int* __restrict__ rel_idx) {
    const int wh = blockIdx.x;
    const int w = wh / HEADS, h = wh % HEADS;
    const float* mrow = mask + (size_t)w * SW * SW;
    float* out = g_mb + (size_t)wh * SW * SW;
    for (int e = threadIdx.x; e < SW * SW; e += blockDim.x)
        out[e] = mrow[e] + bias_table[rel_idx[e] * HEADS + h];
}

// ---------------------------------------------------------------------------
// C[M,N] = A[M,K] @ Wt[N,K]^T + bias[N]   (fp16 operands, fp32 accumulate)
// OutT selects fp32 or fp16 stores in the epilogue.
// ---------------------------------------------------------------------------
template <typename OutT>
__global__ __launch_bounds__(256, 2) void gemm_f16_kernel(
        const __half* __restrict__ A, const __half* __restrict__ Wt,
        const float* __restrict__ bias, OutT* __restrict__ C,
        int M, int N, int K) {
    extern __shared__ __half sh[];
    __half* As = sh;
    __half* Bs = sh + STAGES * BUFH;

    const int tid = threadIdx.x;
    const int lane = tid & 31;
    const int wid = tid >> 5;
    const int wm = (wid >> 2) * 64;
    const int wn = (wid & 3) * 32;
    const int m0 = blockIdx.y * 128;
    const int n0 = blockIdx.x * 128;

    const uint32_t asA = (uint32_t)__cvta_generic_to_shared(As);
    const uint32_t asB = (uint32_t)__cvta_generic_to_shared(Bs);

    const int rowoff = ((lane >> 3) & 1) * 8 + (lane & 7);
    const unsigned aBaseH = (unsigned)((wm + rowoff) * SAH + (lane >> 4) * 8);
    const unsigned bBaseH = (unsigned)((wn + ((lane >> 4) & 1) * 8 + (lane & 7)) * SAH
                                       + ((lane >> 3) & 1) * 8);

    float acc[4][4][4];
#pragma unroll
    for (int mt = 0; mt < 4; mt++)
#pragma unroll
        for (int nt = 0; nt < 4; nt++)
#pragma unroll
            for (int r = 0; r < 4; r++) acc[mt][nt][r] = 0.f;

    const int nIter = K >> 5;

#define ISSUE_TILE(t, s)                                                           \
    do {                                                                           \
        const int k0_ = (t) << 5;                                                  \
        _Pragma("unroll")                                                          \
        for (int i = 0; i < 2; i++) {                                              \
            const int idx = tid + i * 256;                                         \
            const int row = idx >> 2, seg = idx & 3;                               \
            const uint32_t doff = (uint32_t)((s) * BUFH + row * SAH + seg * 8) * 2u; \
            cpasync16(asA + doff, &A[(size_t)(m0 + row) * K + k0_ + seg * 8]);     \
            cpasync16(asB + doff, &Wt[(size_t)(n0 + row) * K + k0_ + seg * 8]);    \
        }                                                                          \
        asm volatile("cp.async.commit_group;");                                    \
    } while (0)

#pragma unroll
    for (int s = 0; s < STAGES - 1; s++) ISSUE_TILE(s, s);

    for (int it = 0; it < nIter; it++) {
        asm volatile("cp.async.wait_group %0;" :: "n"(STAGES - 2));
        __syncthreads();

        const int nt_ = it + STAGES - 1;
        if (nt_ < nIter) ISSUE_TILE(nt_, nt_ & (STAGES - 1));
        else asm volatile("cp.async.commit_group;");

        const int buf = it & (STAGES - 1);
#pragma unroll
        for (int ks = 0; ks < 2; ks++) {
            unsigned afr[4][4];
#pragma unroll
            for (int mt = 0; mt < 4; mt++) {
                uint32_t addr = asA +
                    ((unsigned)(buf * BUFH + mt * 16 * SAH + ks * 16) + aBaseH) * 2u;
                ldsm4(afr[mt][0], afr[mt][1], afr[mt][2], afr[mt][3], addr);
            }
            unsigned bfr[4][2];
#pragma unroll
            for (int p = 0; p < 2; p++) {
                uint32_t addr = asB +
                    ((unsigned)(buf * BUFH + p * 16 * SAH + ks * 16) + bBaseH) * 2u;
                unsigned r0, r1, r2, r3;
                ldsm4(r0, r1, r2, r3, addr);
                bfr[2 * p][0] = r0;     bfr[2 * p][1] = r1;
                bfr[2 * p + 1][0] = r2; bfr[2 * p + 1][1] = r3;
            }
#pragma unroll
            for (int mt = 0; mt < 4; mt++)
#pragma unroll
                for (int nt2 = 0; nt2 < 4; nt2++)
                    mma_f16(acc[mt][nt2], afr[mt], bfr[nt2]);
        }
    }
#undef ISSUE_TILE

#pragma unroll
    for (int mt = 0; mt < 4; mt++) {
        const int r = m0 + wm + mt * 16 + (lane >> 2);
#pragma unroll
        for (int nt = 0; nt < 4; nt++) {
            const int c = n0 + wn + nt * 8 + ((lane & 3) << 1);
            const float b0 = bias[c], b1 = bias[c + 1];
            if constexpr (sizeof(OutT) == 4) {
                *(float2*)&C[(size_t)r * N + c] =
                    make_float2(acc[mt][nt][0] + b0, acc[mt][nt][1] + b1);
                *(float2*)&C[(size_t)(r + 8) * N + c] =
                    make_float2(acc[mt][nt][2] + b0, acc[mt][nt][3] + b1);
            } else {
                *(unsigned*)&C[(size_t)r * N + c] =
                    packh2(acc[mt][nt][0] + b0, acc[mt][nt][1] + b1);
                *(unsigned*)&C[(size_t)(r + 8) * N + c] =
                    packh2(acc[mt][nt][2] + b0, acc[mt][nt][3] + b1);
            }
        }
    }
}

// ---------------------------------------------------------------------------
// Tensor-core attention: one block per (window b, head h), 128 threads.
// 64x64 padded tiles, registers-only softmax, poly exp, no MUFU in hot path.
// ---------------------------------------------------------------------------
__global__ __launch_bounds__(128) void attn_mma_kernel() {
    __shared__ __half Qs[64 * SAH];
    __shared__ __half Ks[64 * SAH];
    __shared__ __half Vs[64 * SAH];

    const int bh = blockIdx.x;
    const int b = bh >> 4;
    const int h = bh & 15;
    const int tid = threadIdx.x;
    const int lane = tid & 31;
    const int w = tid >> 5;
    const float scale = 0.17677669529663689f;

    // stage q/k/v (fp16) rows; zero-fill padding rows 49..63
    {
        const __half* src = g_qkvh + (size_t)b * SW * (3 * DIMC) + h * HD;
        for (int e = tid; e < 64 * 16; e += 128) {
            const int row = e >> 4, dp = (e & 15) * 2;
            unsigned q = 0, k = 0, v = 0;
            if (row < SW) {
                const __half* p = src + (size_t)row * (3 * DIMC) + dp;
                q = *(const unsigned*)(p);
                k = *(const unsigned*)(p + DIMC);
                v = *(const unsigned*)(p + 2 * DIMC);
            }
            *(unsigned*)&Qs[row * SAH + dp] = q;
            *(unsigned*)&Ks[row * SAH + dp] = k;
            *(unsigned*)&Vs[row * SAH + dp] = v;
        }
    }
    __syncthreads();

    const uint32_t sQ = (uint32_t)__cvta_generic_to_shared(Qs);
    const uint32_t sK = (uint32_t)__cvta_generic_to_shared(Ks);
    const uint32_t sV = (uint32_t)__cvta_generic_to_shared(Vs);

    const int rowoff = ((lane >> 3) & 1) * 8 + (lane & 7);
    const unsigned aBase = (unsigned)((w * 16 + rowoff) * SAH + (lane >> 4) * 8);
    const unsigned bBase = (unsigned)((((lane >> 4) & 1) * 8 + (lane & 7)) * SAH
                                      + ((lane >> 3) & 1) * 8);

    // ---- S = Q @ K^T  (64x64, k=32) ----
    float sc[8][4];
#pragma unroll
    for (int nb = 0; nb < 8; nb++)
#pragma unroll
        for (int r = 0; r < 4; r++) sc[nb][r] = 0.f;

#pragma unroll
    for (int ks = 0; ks < 2; ks++) {
        unsigned afr[4];
        ldsm4(afr[0], afr[1], afr[2], afr[3], sQ + (aBase + ks * 16) * 2u);
        unsigned bfr[8][2];
#pragma unroll
        for (int p = 0; p < 4; p++) {
            unsigned r0, r1, r2, r3;
            ldsm4(r0, r1, r2, r3, sK + ((unsigned)(p * 16 * SAH + ks * 16) + bBase) * 2u);
            bfr[2 * p][0] = r0;     bfr[2 * p][1] = r1;
            bfr[2 * p + 1][0] = r2; bfr[2 * p + 1][1] = r3;
        }
#pragma unroll
        for (int nb = 0; nb < 8; nb++) mma_f16(sc[nb], afr, bfr[nb]);
    }

    // ---- mask + bias, softmax in registers ----
    const int rA = w * 16 + (lane >> 2);
    const int rB = rA + 8;
    const float* mbp = g_mb + (size_t)((b & (NWIN - 1)) * HEADS + h) * (SW * SW);

    float mxA = -1e30f, mxB = -1e30f;
#pragma unroll
    for (int nb = 0; nb < 8; nb++) {
        const int c0 = nb * 8 + (lane & 3) * 2;
        const bool vA0 = (rA < SW) && (c0 < SW), vA1 = (rA < SW) && (c0 + 1 < SW);
        const bool vB0 = (rB < SW) && (c0 < SW), vB1 = (rB < SW) && (c0 + 1 < SW);
        sc[nb][0] = vA0 ? fmaf(sc[nb][0], scale, mbp[rA * SW + c0])     : -1e30f;
        sc[nb][1] = vA1 ? fmaf(sc[nb][1], scale, mbp[rA * SW + c0 + 1]) : -1e30f;
        sc[nb][2] = vB0 ? fmaf(sc[nb][2], scale, mbp[rB * SW + c0])     : -1e30f;
        sc[nb][3] = vB1 ? fmaf(sc[nb][3], scale, mbp[rB * SW + c0 + 1]) : -1e30f;
        mxA = fmaxf(mxA, fmaxf(sc[nb][0], sc[nb][1]));
        mxB = fmaxf(mxB, fmaxf(sc[nb][2], sc[nb][3]));
    }
    mxA = fmaxf(mxA, __shfl_xor_sync(0xFFFFFFFFu, mxA, 1));
    mxA = fmaxf(mxA, __shfl_xor_sync(0xFFFFFFFFu, mxA, 2));
    mxB = fmaxf(mxB, __shfl_xor_sync(0xFFFFFFFFu, mxB, 1));
    mxB = fmaxf(mxB, __shfl_xor_sync(0xFFFFFFFFu, mxB, 2));

    float sA = 0.f, sB = 0.f;
#pragma unroll
    for (int nb = 0; nb < 8; nb++) {
        sc[nb][0] = fast_exp(sc[nb][0] - mxA);
        sc[nb][1] = fast_exp(sc[nb][1] - mxA);
        sc[nb][2] = fast_exp(sc[nb][2] - mxB);
        sc[nb][3] = fast_exp(sc[nb][3] - mxB);
        sA += sc[nb][0] + sc[nb][1];
        sB += sc[nb][2] + sc[nb][3];
    }
    sA += __shfl_xor_sync(0xFFFFFFFFu, sA, 1);
    sA += __shfl_xor_sync(0xFFFFFFFFu, sA, 2);
    sB += __shfl_xor_sync(0xFFFFFFFFu, sB, 1);
    sB += __shfl_xor_sync(0xFFFFFFFFu, sB, 2);
    const float invA = __fdividef(1.f, sA);
    const float invB = __fdividef(1.f, sB);

    // ---- O = P @ V  (64x32, k=64); P A-frags built from S C-frags ----
    float o[4][4];
#pragma unroll
    for (int db = 0; db < 4; db++)
#pragma unroll
        for (int r = 0; r < 4; r++) o[db][r] = 0.f;

#pragma unroll
    for (int j = 0; j < 4; j++) {
        unsigned pf[4];
        pf[0] = packh2(sc[2 * j][0] * invA, sc[2 * j][1] * invA);
        pf[1] = packh2(sc[2 * j][2] * invB, sc[2 * j][3] * invB);
        pf[2] = packh2(sc[2 * j + 1][0] * invA, sc[2 * j + 1][1] * invA);
        pf[3] = packh2(sc[2 * j + 1][2] * invB, sc[2 * j + 1][3] * invB);

        // V fragments via ldmatrix.trans from Vs[key][d]
        const unsigned vrow = (unsigned)(16 * j + (lane & 7) + 8 * ((lane >> 3) & 1));
        unsigned vf[4][2];
#pragma unroll
        for (int nb2 = 0; nb2 < 2; nb2++) {
            unsigned r0, r1, r2, r3;
            uint32_t addr = sV + (vrow * SAH + nb2 * 16 + ((lane >> 4) & 1) * 8) * 2u;
            ldsm4t(r0, r1, r2, r3, addr);
            vf[2 * nb2][0] = r0;     vf[2 * nb2][1] = r1;
            vf[2 * nb2 + 1][0] = r2; vf[2 * nb2 + 1][1] = r3;
        }
#pragma unroll
        for (int db = 0; db < 4; db++) mma_f16(o[db], pf, vf[db]);
    }

    // ---- store O (fp16) ----
    if (rA < SW) {
        __half* out = g_atth + ((size_t)(b * SW + rA)) * DIMC + h * HD;
#pragma unroll
        for (int db = 0; db < 4; db++)
            *(unsigned*)&out[db * 8 + (lane & 3) * 2] = packh2(o[db][0], o[db][1]);
    }
    if (rB < SW) {
        __half* out = g_atth + ((size_t)(b * SW + rB)) * DIMC + h * HD;
#pragma unroll
        for (int db = 0; db < 4; db++)
            *(unsigned*)&out[db * 8 + (lane & 3) * 2] = packh2(o[db][2], o[db][3]);
    }
}

// ---------------------------------------------------------------------------
extern "C" void kernel_launch(void* const* d_in, const int* in_sizes, int n_in,
                              void* d_out, int out_size) {
    const float* x          = (const float*)d_in[0];
    const float* mask       = (const float*)d_in[1];
    const float* qkv_w      = (const float*)d_in[2];
    const float* qkv_b      = (const float*)d_in[3];
    const float* proj_w     = (const float*)d_in[4];
    const float* proj_b     = (const float*)d_in[5];
    const float* bias_table = (const float*)d_in[6];
    const int*   rel_idx    = (const int*)d_in[7];

    static __half* qkvh_ptr = nullptr;
    static __half* atth_ptr = nullptr;
    static __half* xh_ptr = nullptr;
    static __half* wtqh_ptr = nullptr;
    static __half* wtph_ptr = nullptr;
    if (!qkvh_ptr) {
        cudaGetSymbolAddress((void**)&qkvh_ptr, g_qkvh);
        cudaGetSymbolAddress((void**)&atth_ptr, g_atth);
        cudaGetSymbolAddress((void**)&xh_ptr, g_xh);
        cudaGetSymbolAddress((void**)&wtqh_ptr, g_wtqh);
        cudaGetSymbolAddress((void**)&wtph_ptr, g_wtph);
        cudaFuncSetAttribute(gemm_f16_kernel<__half>,
                             cudaFuncAttributeMaxDynamicSharedMemorySize, GEMM_SMEM);
        cudaFuncSetAttribute(gemm_f16_kernel<float>,
                             cudaFuncAttributeMaxDynamicSharedMemorySize, GEMM_SMEM);
    }

    // 0) pre-pass conversions
    {
        const int n4 = TOKENS * DIMC / 4;
        cvt_h_kernel<<<(n4 + 255) / 256, 256>>>((const float4*)x, (__half2*)xh_ptr, n4);
        tconv_h_kernel<<<dim3(3 * DIMC / 32, DIMC / 32), dim3(32, 8)>>>(
            qkv_w, wtqh_ptr, DIMC, 3 * DIMC);
        tconv_h_kernel<<<dim3(DIMC / 32, DIMC / 32), dim3(32, 8)>>>(
            proj_w, wtph_ptr, DIMC, DIMC);
        mb_kernel<<<NWIN * HEADS, 256>>>(mask, bias_table, rel_idx);
    }

    // 1) QKV projection -> fp16
    gemm_f16_kernel<__half><<<dim3(3 * DIMC / 128, TOKENS / 128), 256, GEMM_SMEM>>>(
        xh_ptr, wtqh_ptr, qkv_b, qkvh_ptr, TOKENS, 3 * DIMC, DIMC);

    // 2) Tensor-core windowed attention
    attn_mma_kernel<<<BWIN * HEADS, 128>>>();

    // 3) Output projection -> fp32 d_out
    gemm_f16_kernel<float><<<dim3(DIMC / 128, TOKENS / 128), 256, GEMM_SMEM>>>(
        atth_ptr, wtph_ptr, proj_b, (float*)d_out, TOKENS, DIMC, DIMC);
}

// round 10
// speedup vs baseline: 7.1510x; 1.0281x over previous
#include <cuda_runtime.h>
#include <cuda_fp16.h>
#include <cstdint>

#define DIMC 512
#define HEADS 16
#define HD 32
#define SW 49
#define NWIN 64
#define BWIN 2048
#define TOKENS (BWIN * SW)   // 100352

#define SAH 40                 // GEMM smem row stride in halfs
#define BUFH (128 * SAH)
#define STAGES 4
#define GEMM_SMEM (2 * STAGES * BUFH * 2)   // bytes = 81920

#define ASA 56                 // attention smem row stride in halfs (112B: 16B-mult, ldsm-clean)
#define MBROW 52               // padded mb row (floats)
#define MBTILE (SW * MBROW)    // floats per (w,h) tile = 2548 (10192 B, 16B-mult)

// Scratch (static device globals; no runtime allocation)
__device__ __half g_qkvh[(size_t)TOKENS * 3 * DIMC];   // qkv out, fp16
__device__ __half g_atth[(size_t)TOKENS * DIMC];       // attention out, fp16
__device__ __half g_xh[(size_t)TOKENS * DIMC];         // x, fp16
__device__ __half g_wtqh[(size_t)(3 * DIMC) * DIMC];   // qkv_w^T [n][k] fp16
__device__ __half g_wtph[(size_t)DIMC * DIMC];         // proj_w^T [n][k] fp16
__device__ float  g_mb[(size_t)NWIN * HEADS * MBTILE + 64]; // fused mask+bias, padded rows

// ---------------------------------------------------------------------------
__device__ __forceinline__ void mma_f16(float* d, const unsigned* a, const unsigned* b) {
    asm volatile(
        "mma.sync.aligned.m16n8k16.row.col.f32.f16.f16.f32 "
        "{%0,%1,%2,%3}, {%4,%5,%6,%7}, {%8,%9}, {%0,%1,%2,%3};"
        : "+f"(d[0]), "+f"(d[1]), "+f"(d[2]), "+f"(d[3])
        : "r"(a[0]), "r"(a[1]), "r"(a[2]), "r"(a[3]), "r"(b[0]), "r"(b[1]));
}

__device__ __forceinline__ void ldsm4(unsigned& r0, unsigned& r1,
                                      unsigned& r2, unsigned& r3, uint32_t addr) {
    asm volatile("ldmatrix.sync.aligned.m8n8.x4.shared.b16 {%0,%1,%2,%3}, [%4];"
                 : "=r"(r0), "=r"(r1), "=r"(r2), "=r"(r3) : "r"(addr));
}

__device__ __forceinline__ void ldsm4t(unsigned& r0, unsigned& r1,
                                       unsigned& r2, unsigned& r3, uint32_t addr) {
    asm volatile("ldmatrix.sync.aligned.m8n8.x4.trans.shared.b16 {%0,%1,%2,%3}, [%4];"
                 : "=r"(r0), "=r"(r1), "=r"(r2), "=r"(r3) : "r"(addr));
}

__device__ __forceinline__ void cpasync16(uint32_t dst, const void* src) {
    asm volatile("cp.async.cg.shared.global [%0], [%1], 16;" :: "r"(dst), "l"(src));
}

__device__ __forceinline__ unsigned packh2(float lo, float hi) {
    __half2 t = __floats2half2_rn(lo, hi);
    return *(unsigned*)&t;
}

// exp on the FMA/ALU pipes (no MUFU)
__device__ __forceinline__ float fast_exp(float z) {
    z = fmaxf(z, -80.f);
    float y = z * 1.44269504088896f;
    int i = __float2int_rn(y);
    float f = y - (float)i;
    float p = 0.0013333558146f;
    p = fmaf(p, f, 0.0096181291076f);
    p = fmaf(p, f, 0.0555041086648f);
    p = fmaf(p, f, 0.2402265069591f);
    p = fmaf(p, f, 0.6931471805599f);
    p = fmaf(p, f, 1.0f);
    return p * __int_as_float((i + 127) << 23);
}

// ---------------------------------------------------------------------------
// Pre-pass kernels
// ---------------------------------------------------------------------------
__global__ void cvt_h_kernel(const float4* __restrict__ src,
                             __half2* __restrict__ dst, int n4) {
    int i = blockIdx.x * blockDim.x + threadIdx.x;
    if (i < n4) {
        float4 v = src[i];
        dst[2 * i]     = __floats2half2_rn(v.x, v.y);
        dst[2 * i + 1] = __floats2half2_rn(v.z, v.w);
    }
}

__global__ void tconv_h_kernel(const float* __restrict__ W, __half* __restrict__ Wt,
                               int K, int N) {
    __shared__ float t[32][33];
    const int n0 = blockIdx.x * 32, k0 = blockIdx.y * 32;
    const int tx = threadIdx.x, ty = threadIdx.y;
#pragma unroll
    for (int r = 0; r < 32; r += 8)
        t[ty + r][tx] = W[(size_t)(k0 + ty + r) * N + n0 + tx];
    __syncthreads();
#pragma unroll
    for (int r = 0; r < 32; r += 8)
        Wt[(size_t)(n0 + ty + r) * K + k0 + tx] = __float2half_rn(t[tx][ty + r]);
}

// mb tile with rows padded to MBROW floats (16B-aligned rows for cp.async)
__global__ void mb_kernel(const float* __restrict__ mask,
                          const float* __restrict__ bias_table,
                          const int* __restrict__ rel_idx) {
    const int wh = blockIdx.x;
    const int w = wh / HEADS, h = wh % HEADS;
    const float* mrow = mask + (size_t)w * SW * SW;
    float* out = g_mb + (size_t)wh * MBTILE;
    for (int e = threadIdx.x; e < SW * SW; e += blockDim.x) {
        const int i = e / SW, j = e % SW;
        out[i * MBROW + j] = mrow[e] + bias_table[rel_idx[e] * HEADS + h];
    }
}

// ---------------------------------------------------------------------------
// C[M,N] = A[M,K] @ Wt[N,K]^T + bias[N]   (fp16 operands, fp32 accumulate)
// ---------------------------------------------------------------------------
template <typename OutT>
__global__ __launch_bounds__(256, 2) void gemm_f16_kernel(
        const __half* __restrict__ A, const __half* __restrict__ Wt,
        const float* __restrict__ bias, OutT* __restrict__ C,
        int M, int N, int K) {
    extern __shared__ __half sh[];
    __half* As = sh;
    __half* Bs = sh + STAGES * BUFH;

    const int tid = threadIdx.x;
    const int lane = tid & 31;
    const int wid = tid >> 5;
    const int wm = (wid >> 2) * 64;
    const int wn = (wid & 3) * 32;
    const int m0 = blockIdx.y * 128;
    const int n0 = blockIdx.x * 128;

    const uint32_t asA = (uint32_t)__cvta_generic_to_shared(As);
    const uint32_t asB = (uint32_t)__cvta_generic_to_shared(Bs);

    const int rowoff = ((lane >> 3) & 1) * 8 + (lane & 7);
    const unsigned aBaseH = (unsigned)((wm + rowoff) * SAH + (lane >> 4) * 8);
    const unsigned bBaseH = (unsigned)((wn + ((lane >> 4) & 1) * 8 + (lane & 7)) * SAH
                                       + ((lane >> 3) & 1) * 8);

    float acc[4][4][4];
#pragma unroll
    for (int mt = 0; mt < 4; mt++)
#pragma unroll
        for (int nt = 0; nt < 4; nt++)
#pragma unroll
            for (int r = 0; r < 4; r++) acc[mt][nt][r] = 0.f;

    const int nIter = K >> 5;

#define ISSUE_TILE(t, s)                                                           \
    do {                                                                           \
        const int k0_ = (t) << 5;                                                  \
        _Pragma("unroll")                                                          \
        for (int i = 0; i < 2; i++) {                                              \
            const int idx = tid + i * 256;                                         \
            const int row = idx >> 2, seg = idx & 3;                               \
            const uint32_t doff = (uint32_t)((s) * BUFH + row * SAH + seg * 8) * 2u; \
            cpasync16(asA + doff, &A[(size_t)(m0 + row) * K + k0_ + seg * 8]);     \
            cpasync16(asB + doff, &Wt[(size_t)(n0 + row) * K + k0_ + seg * 8]);    \
        }                                                                          \
        asm volatile("cp.async.commit_group;");                                    \
    } while (0)

#pragma unroll
    for (int s = 0; s < STAGES - 1; s++) ISSUE_TILE(s, s);

    for (int it = 0; it < nIter; it++) {
        asm volatile("cp.async.wait_group %0;" :: "n"(STAGES - 2));
        __syncthreads();

        const int nt_ = it + STAGES - 1;
        if (nt_ < nIter) ISSUE_TILE(nt_, nt_ & (STAGES - 1));
        else asm volatile("cp.async.commit_group;");

        const int buf = it & (STAGES - 1);
#pragma unroll
        for (int ks = 0; ks < 2; ks++) {
            unsigned afr[4][4];
#pragma unroll
            for (int mt = 0; mt < 4; mt++) {
                uint32_t addr = asA +
                    ((unsigned)(buf * BUFH + mt * 16 * SAH + ks * 16) + aBaseH) * 2u;
                ldsm4(afr[mt][0], afr[mt][1], afr[mt][2], afr[mt][3], addr);
            }
            unsigned bfr[4][2];
#pragma unroll
            for (int p = 0; p < 2; p++) {
                uint32_t addr = asB +
                    ((unsigned)(buf * BUFH + p * 16 * SAH + ks * 16) + bBaseH) * 2u;
                unsigned r0, r1, r2, r3;
                ldsm4(r0, r1, r2, r3, addr);
                bfr[2 * p][0] = r0;     bfr[2 * p][1] = r1;
                bfr[2 * p + 1][0] = r2; bfr[2 * p + 1][1] = r3;
            }
#pragma unroll
            for (int mt = 0; mt < 4; mt++)
#pragma unroll
                for (int nt2 = 0; nt2 < 4; nt2++)
                    mma_f16(acc[mt][nt2], afr[mt], bfr[nt2]);
        }
    }
#undef ISSUE_TILE

#pragma unroll
    for (int mt = 0; mt < 4; mt++) {
        const int r = m0 + wm + mt * 16 + (lane >> 2);
#pragma unroll
        for (int nt = 0; nt < 4; nt++) {
            const int c = n0 + wn + nt * 8 + ((lane & 3) << 1);
            const float b0 = bias[c], b1 = bias[c + 1];
            if constexpr (sizeof(OutT) == 4) {
                *(float2*)&C[(size_t)r * N + c] =
                    make_float2(acc[mt][nt][0] + b0, acc[mt][nt][1] + b1);
                *(float2*)&C[(size_t)(r + 8) * N + c] =
                    make_float2(acc[mt][nt][2] + b0, acc[mt][nt][3] + b1);
            } else {
                *(unsigned*)&C[(size_t)r * N + c] =
                    packh2(acc[mt][nt][0] + b0, acc[mt][nt][1] + b1);
                *(unsigned*)&C[(size_t)(r + 8) * N + c] =
                    packh2(acc[mt][nt][2] + b0, acc[mt][nt][3] + b1);
            }
        }
    }
}

// ---------------------------------------------------------------------------
// Tensor-core attention: one block per (window b, head h), 128 threads.
// 16B-vector staging; mb tile prefetched to smem via cp.async.
// ---------------------------------------------------------------------------
__global__ __launch_bounds__(128) void attn_mma_kernel() {
    __shared__ __half Qs[64 * ASA];
    __shared__ __half Ks[64 * ASA];
    __shared__ __half Vs[64 * ASA];
    __shared__ float  Mbs[MBTILE];

    const int bh = blockIdx.x;
    const int b = bh >> 4;
    const int h = bh & 15;
    const int tid = threadIdx.x;
    const int lane = tid & 31;
    const int w = tid >> 5;
    const float scale = 0.17677669529663689f;

    const uint32_t sQ = (uint32_t)__cvta_generic_to_shared(Qs);
    const uint32_t sK = (uint32_t)__cvta_generic_to_shared(Ks);
    const uint32_t sV = (uint32_t)__cvta_generic_to_shared(Vs);
    const uint32_t sM = (uint32_t)__cvta_generic_to_shared(Mbs);

    // mb tile prefetch: 637 x 16B chunks, contiguous
    {
        const char* src = (const char*)(g_mb + (size_t)((b & (NWIN - 1)) * HEADS + h) * MBTILE);
        for (int i = tid; i < (MBTILE * 4) / 16; i += 128)
            cpasync16(sM + i * 16, src + i * 16);
        asm volatile("cp.async.commit_group;");
    }

    // stage q/k/v rows (16B vectors); zero-fill rows 49..63
    {
        const __half* src = g_qkvh + (size_t)b * SW * (3 * DIMC) + h * HD;
#pragma unroll
        for (int i = 0; i < 2; i++) {
            const int e = tid + i * 128;
            const int row = e >> 2, seg = (e & 3) * 8;   // 8 halfs = 16B
            uint4 q = {0, 0, 0, 0}, k = q, v = q;
            if (row < SW) {
                const __half* p = src + (size_t)row * (3 * DIMC) + seg;
                q = *(const uint4*)(p);
                k = *(const uint4*)(p + DIMC);
                v = *(const uint4*)(p + 2 * DIMC);
            }
            *(uint4*)&Qs[row * ASA + seg] = q;
            *(uint4*)&Ks[row * ASA + seg] = k;
            *(uint4*)&Vs[row * ASA + seg] = v;
        }
    }
    asm volatile("cp.async.wait_group 0;");
    __syncthreads();

    const int rowoff = ((lane >> 3) & 1) * 8 + (lane & 7);
    const unsigned aBase = (unsigned)((w * 16 + rowoff) * ASA + (lane >> 4) * 8);
    const unsigned bBase = (unsigned)((((lane >> 4) & 1) * 8 + (lane & 7)) * ASA
                                      + ((lane >> 3) & 1) * 8);

    // ---- S = Q @ K^T  (64x64, k=32) ----
    float sc[8][4];
#pragma unroll
    for (int nb = 0; nb < 8; nb++)
#pragma unroll
        for (int r = 0; r < 4; r++) sc[nb][r] = 0.f;

#pragma unroll
    for (int ks = 0; ks < 2; ks++) {
        unsigned afr[4];
        ldsm4(afr[0], afr[1], afr[2], afr[3], sQ + (aBase + ks * 16) * 2u);
        unsigned bfr[8][2];
#pragma unroll
        for (int p = 0; p < 4; p++) {
            unsigned r0, r1, r2, r3;
            ldsm4(r0, r1, r2, r3, sK + ((unsigned)(p * 16 * ASA + ks * 16) + bBase) * 2u);
            bfr[2 * p][0] = r0;     bfr[2 * p][1] = r1;
            bfr[2 * p + 1][0] = r2; bfr[2 * p + 1][1] = r3;
        }
#pragma unroll
        for (int nb = 0; nb < 8; nb++) mma_f16(sc[nb], afr, bfr[nb]);
    }

    // ---- mask + bias (from smem), softmax in registers ----
    const int rA = w * 16 + (lane >> 2);
    const int rB = rA + 8;

    float mxA = -1e30f, mxB = -1e30f;
#pragma unroll
    for (int nb = 0; nb < 8; nb++) {
        const int c0 = nb * 8 + (lane & 3) * 2;
        const bool vA0 = (rA < SW) && (c0 < SW), vA1 = (rA < SW) && (c0 + 1 < SW);
        const bool vB0 = (rB < SW) && (c0 < SW), vB1 = (rB < SW) && (c0 + 1 < SW);
        sc[nb][0] = vA0 ? fmaf(sc[nb][0], scale, Mbs[rA * MBROW + c0])     : -1e30f;
        sc[nb][1] = vA1 ? fmaf(sc[nb][1], scale, Mbs[rA * MBROW + c0 + 1]) : -1e30f;
        sc[nb][2] = vB0 ? fmaf(sc[nb][2], scale, Mbs[rB * MBROW + c0])     : -1e30f;
        sc[nb][3] = vB1 ? fmaf(sc[nb][3], scale, Mbs[rB * MBROW + c0 + 1]) : -1e30f;
        mxA = fmaxf(mxA, fmaxf(sc[nb][0], sc[nb][1]));
        mxB = fmaxf(mxB, fmaxf(sc[nb][2], sc[nb][3]));
    }
    mxA = fmaxf(mxA, __shfl_xor_sync(0xFFFFFFFFu, mxA, 1));
    mxA = fmaxf(mxA, __shfl_xor_sync(0xFFFFFFFFu, mxA, 2));
    mxB = fmaxf(mxB, __shfl_xor_sync(0xFFFFFFFFu, mxB, 1));
    mxB = fmaxf(mxB, __shfl_xor_sync(0xFFFFFFFFu, mxB, 2));

    float sA = 0.f, sB = 0.f;
#pragma unroll
    for (int nb = 0; nb < 8; nb++) {
        sc[nb][0] = fast_exp(sc[nb][0] - mxA);
        sc[nb][1] = fast_exp(sc[nb][1] - mxA);
        sc[nb][2] = fast_exp(sc[nb][2] - mxB);
        sc[nb][3] = fast_exp(sc[nb][3] - mxB);
        sA += sc[nb][0] + sc[nb][1];
        sB += sc[nb][2] + sc[nb][3];
    }
    sA += __shfl_xor_sync(0xFFFFFFFFu, sA, 1);
    sA += __shfl_xor_sync(0xFFFFFFFFu, sA, 2);
    sB += __shfl_xor_sync(0xFFFFFFFFu, sB, 1);
    sB += __shfl_xor_sync(0xFFFFFFFFu, sB, 2);
    const float invA = __fdividef(1.f, sA);
    const float invB = __fdividef(1.f, sB);

    // ---- O = P @ V  (64x32, k=64); P A-frags from S C-frags ----
    float o[4][4];
#pragma unroll
    for (int db = 0; db < 4; db++)
#pragma unroll
        for (int r = 0; r < 4; r++) o[db][r] = 0.f;

#pragma unroll
    for (int j = 0; j < 4; j++) {
        unsigned pf[4];
        pf[0] = packh2(sc[2 * j][0] * invA, sc[2 * j][1] * invA);
        pf[1] = packh2(sc[2 * j][2] * invB, sc[2 * j][3] * invB);
        pf[2] = packh2(sc[2 * j + 1][0] * invA, sc[2 * j + 1][1] * invA);
        pf[3] = packh2(sc[2 * j + 1][2] * invB, sc[2 * j + 1][3] * invB);

        const unsigned vrow = (unsigned)(16 * j + (lane & 7) + 8 * ((lane >> 3) & 1));
        unsigned vf[4][2];
#pragma unroll
        for (int nb2 = 0; nb2 < 2; nb2++) {
            unsigned r0, r1, r2, r3;
            uint32_t addr = sV + (vrow * ASA + nb2 * 16 + ((lane >> 4) & 1) * 8) * 2u;
            ldsm4t(r0, r1, r2, r3, addr);
            vf[2 * nb2][0] = r0;     vf[2 * nb2][1] = r1;
            vf[2 * nb2 + 1][0] = r2; vf[2 * nb2 + 1][1] = r3;
        }
#pragma unroll
        for (int db = 0; db < 4; db++) mma_f16(o[db], pf, vf[db]);
    }

    // ---- store O (fp16) ----
    if (rA < SW) {
        __half* out = g_atth + ((size_t)(b * SW + rA)) * DIMC + h * HD;
#pragma unroll
        for (int db = 0; db < 4; db++)
            *(unsigned*)&out[db * 8 + (lane & 3) * 2] = packh2(o[db][0], o[db][1]);
    }
    if (rB < SW) {
        __half* out = g_atth + ((size_t)(b * SW + rB)) * DIMC + h * HD;
#pragma unroll
        for (int db = 0; db < 4; db++)
            *(unsigned*)&out[db * 8 + (lane & 3) * 2] = packh2(o[db][2], o[db][3]);
    }
}

// ---------------------------------------------------------------------------
extern "C" void kernel_launch(void* const* d_in, const int* in_sizes, int n_in,
                              void* d_out, int out_size) {
    const float* x          = (const float*)d_in[0];
    const float* mask       = (const float*)d_in[1];
    const float* qkv_w      = (const float*)d_in[2];
    const float* qkv_b      = (const float*)d_in[3];
    const float* proj_w     = (const float*)d_in[4];
    const float* proj_b     = (const float*)d_in[5];
    const float* bias_table = (const float*)d_in[6];
    const int*   rel_idx    = (const int*)d_in[7];

    static __half* qkvh_ptr = nullptr;
    static __half* atth_ptr = nullptr;
    static __half* xh_ptr = nullptr;
    static __half* wtqh_ptr = nullptr;
    static __half* wtph_ptr = nullptr;
    if (!qkvh_ptr) {
        cudaGetSymbolAddress((void**)&qkvh_ptr, g_qkvh);
        cudaGetSymbolAddress((void**)&atth_ptr, g_atth);
        cudaGetSymbolAddress((void**)&xh_ptr, g_xh);
        cudaGetSymbolAddress((void**)&wtqh_ptr, g_wtqh);
        cudaGetSymbolAddress((void**)&wtph_ptr, g_wtph);
        cudaFuncSetAttribute(gemm_f16_kernel<__half>,
                             cudaFuncAttributeMaxDynamicSharedMemorySize, GEMM_SMEM);
        cudaFuncSetAttribute(gemm_f16_kernel<float>,
                             cudaFuncAttributeMaxDynamicSharedMemorySize, GEMM_SMEM);
    }

    // 0) pre-pass conversions
    {
        const int n4 = TOKENS * DIMC / 4;
        cvt_h_kernel<<<(n4 + 255) / 256, 256>>>((const float4*)x, (__half2*)xh_ptr, n4);
        tconv_h_kernel<<<dim3(3 * DIMC / 32, DIMC / 32), dim3(32, 8)>>>(
            qkv_w, wtqh_ptr, DIMC, 3 * DIMC);
        tconv_h_kernel<<<dim3(DIMC / 32, DIMC / 32), dim3(32, 8)>>>(
            proj_w, wtph_ptr, DIMC, DIMC);
        mb_kernel<<<NWIN * HEADS, 256>>>(mask, bias_table, rel_idx);
    }

    // 1) QKV projection -> fp16
    gemm_f16_kernel<__half><<<dim3(3 * DIMC / 128, TOKENS / 128), 256, GEMM_SMEM>>>(
        xh_ptr, wtqh_ptr, qkv_b, qkvh_ptr, TOKENS, 3 * DIMC, DIMC);

    // 2) Tensor-core windowed attention
    attn_mma_kernel<<<BWIN * HEADS, 128>>>();

    // 3) Output projection -> fp32 d_out
    gemm_f16_kernel<float><<<dim3(DIMC / 128, TOKENS / 128), 256, GEMM_SMEM>>>(
        atth_ptr, wtph_ptr, proj_b, (float*)d_out, TOKENS, DIMC, DIMC);
}